// round 1
// baseline (speedup 1.0000x reference)
#include <cuda_runtime.h>
#include <math.h>

#define DIMN 2048
#define NR   16384
#define LN_EPS 1e-5f

// ---------------- scratch (device globals; no allocation allowed) ----------------
__device__ float g_v[(size_t)NR * DIMN];       // v = x @ V^T
__device__ float g_y[(size_t)NR * DIMN];       // y = x @ Wf^T (general path)
__device__ float g_fast[(size_t)NR * DIMN];    // fast_out (general path)
__device__ float g_hebb[(size_t)DIMN * DIMN];  // hebb (general path)
__device__ float g_wfnew[(size_t)DIMN * DIMN]; // Wf_new (general path)
__device__ float g_colsq[DIMN];                // column sum of y*y (general path)
__device__ float g_px[1024];                   // x sum partials
__device__ float g_pxx[1024];                  // x sumsq partials
__device__ float g_pw[512];                    // W_slow sumsq partials
__device__ int   g_pf[512];                    // W_fast nonzero-count partials
__device__ float g_pabs[2048];                 // sum|v| partials (one per GEMM block)
__device__ float g_ctrl[3];
__device__ int   g_flag;

__device__ __forceinline__ float sigmoidf_(float x) { return 1.0f / (1.0f + expf(-x)); }

// ---------------- stats over x: sum, sumsq (deterministic partials) ----------------
__global__ __launch_bounds__(256) void k_stats_x(const float4* __restrict__ x, int n4) {
    float s = 0.f, s2 = 0.f;
    for (int i = blockIdx.x * blockDim.x + threadIdx.x; i < n4; i += gridDim.x * blockDim.x) {
        float4 t = x[i];
        s  += t.x + t.y + t.z + t.w;
        s2 += t.x * t.x + t.y * t.y + t.z * t.z + t.w * t.w;
    }
#pragma unroll
    for (int o = 16; o; o >>= 1) {
        s  += __shfl_down_sync(0xffffffffu, s, o);
        s2 += __shfl_down_sync(0xffffffffu, s2, o);
    }
    __shared__ float sh1[8], sh2[8];
    if ((threadIdx.x & 31) == 0) { sh1[threadIdx.x >> 5] = s; sh2[threadIdx.x >> 5] = s2; }
    __syncthreads();
    if (threadIdx.x == 0) {
        float a = 0.f, b = 0.f;
        for (int i = 0; i < 8; i++) { a += sh1[i]; b += sh2[i]; }
        g_px[blockIdx.x] = a;
        g_pxx[blockIdx.x] = b;
    }
}

// ---------------- stats over W_slow (sumsq) and W_fast (nonzero count) ----------------
__global__ __launch_bounds__(256) void k_stats_w(const float4* __restrict__ ws,
                                                 const float4* __restrict__ wf, int n4) {
    float s2 = 0.f;
    int cnt = 0;
    for (int i = blockIdx.x * blockDim.x + threadIdx.x; i < n4; i += gridDim.x * blockDim.x) {
        float4 a = ws[i];
        s2 += a.x * a.x + a.y * a.y + a.z * a.z + a.w * a.w;
        float4 b = wf[i];
        cnt += (b.x != 0.f) + (b.y != 0.f) + (b.z != 0.f) + (b.w != 0.f);
    }
#pragma unroll
    for (int o = 16; o; o >>= 1) {
        s2  += __shfl_down_sync(0xffffffffu, s2, o);
        cnt += __shfl_down_sync(0xffffffffu, cnt, o);
    }
    __shared__ float sh1[8];
    __shared__ int   sh2[8];
    if ((threadIdx.x & 31) == 0) { sh1[threadIdx.x >> 5] = s2; sh2[threadIdx.x >> 5] = cnt; }
    __syncthreads();
    if (threadIdx.x == 0) {
        float a = 0.f; int b = 0;
        for (int i = 0; i < 8; i++) { a += sh1[i]; b += sh2[i]; }
        g_pw[blockIdx.x] = a;
        g_pf[blockIdx.x] = b;
    }
}

// ---------------- C[M,N] = A[M,K] @ B[N,K]^T  (both K-major) ----------------
// 128x128 tile, BK=8, 256 threads, 8x8 per thread, double-buffered smem.
template <bool ABS, bool FLAGGED>
__global__ __launch_bounds__(256, 2) void sgemm_nt(const float* __restrict__ A,
                                                   const float* __restrict__ B,
                                                   float* __restrict__ C,
                                                   int M, int N, int K) {
    if (FLAGGED) { if (g_flag == 0) return; }
    constexpr int BM = 128, BN = 128, BK = 8;
    __shared__ float As[2][BK][BM];
    __shared__ float Bs[2][BK][BN];

    const int tid = threadIdx.x;
    const int m0 = blockIdx.y * BM;
    const int n0 = blockIdx.x * BN;
    const int lr = tid >> 1;            // 0..127
    const int lc = (tid & 1) * 4;       // 0 or 4
    const int tx = tid & 15;            // n-tile
    const int ty = tid >> 4;            // m-tile

    const float* Aptr = A + (size_t)(m0 + lr) * K + lc;
    const float* Bptr = B + (size_t)(n0 + lr) * K + lc;

    float acc[8][8] = {};

    float4 pa = *(const float4*)Aptr;
    float4 pb = *(const float4*)Bptr;
    As[0][lc + 0][lr] = pa.x; As[0][lc + 1][lr] = pa.y; As[0][lc + 2][lr] = pa.z; As[0][lc + 3][lr] = pa.w;
    Bs[0][lc + 0][lr] = pb.x; Bs[0][lc + 1][lr] = pb.y; Bs[0][lc + 2][lr] = pb.z; Bs[0][lc + 3][lr] = pb.w;
    __syncthreads();

    const int T = K / BK;
    int buf = 0;
    for (int t = 0; t < T; ++t) {
        const bool has = (t + 1 < T);
        if (has) {
            pa = *(const float4*)(Aptr + (t + 1) * BK);
            pb = *(const float4*)(Bptr + (t + 1) * BK);
        }
#pragma unroll
        for (int k = 0; k < BK; ++k) {
            float4 a0 = *(const float4*)&As[buf][k][ty * 8];
            float4 a1 = *(const float4*)&As[buf][k][ty * 8 + 4];
            float4 b0 = *(const float4*)&Bs[buf][k][tx * 8];
            float4 b1 = *(const float4*)&Bs[buf][k][tx * 8 + 4];
            float av[8] = {a0.x, a0.y, a0.z, a0.w, a1.x, a1.y, a1.z, a1.w};
            float bv[8] = {b0.x, b0.y, b0.z, b0.w, b1.x, b1.y, b1.z, b1.w};
#pragma unroll
            for (int i = 0; i < 8; i++)
#pragma unroll
                for (int j = 0; j < 8; j++) acc[i][j] += av[i] * bv[j];
        }
        if (has) {
            int w = buf ^ 1;
            As[w][lc + 0][lr] = pa.x; As[w][lc + 1][lr] = pa.y; As[w][lc + 2][lr] = pa.z; As[w][lc + 3][lr] = pa.w;
            Bs[w][lc + 0][lr] = pb.x; Bs[w][lc + 1][lr] = pb.y; Bs[w][lc + 2][lr] = pb.z; Bs[w][lc + 3][lr] = pb.w;
            __syncthreads();
            buf = w;
        }
    }

    float asum = 0.f;
#pragma unroll
    for (int i = 0; i < 8; i++) {
        size_t off = (size_t)(m0 + ty * 8 + i) * N + n0 + tx * 8;
        float4 o0 = make_float4(acc[i][0], acc[i][1], acc[i][2], acc[i][3]);
        float4 o1 = make_float4(acc[i][4], acc[i][5], acc[i][6], acc[i][7]);
        *(float4*)&C[off] = o0;
        *(float4*)&C[off + 4] = o1;
        if (ABS) {
            asum += fabsf(o0.x) + fabsf(o0.y) + fabsf(o0.z) + fabsf(o0.w)
                  + fabsf(o1.x) + fabsf(o1.y) + fabsf(o1.z) + fabsf(o1.w);
        }
    }
    if (ABS) {
#pragma unroll
        for (int o = 16; o; o >>= 1) asum += __shfl_down_sync(0xffffffffu, asum, o);
        __shared__ float redA[8];
        if ((tid & 31) == 0) redA[tid >> 5] = asum;
        __syncthreads();
        if (tid == 0) {
            float s = 0.f;
            for (int i = 0; i < 8; i++) s += redA[i];
            g_pabs[blockIdx.y * gridDim.x + blockIdx.x] = s;
        }
    }
}

// ---------------- regulator: reduce partials + tiny MLP (1 block) ----------------
__device__ __forceinline__ double blockReduce256d(double v, double* sh) {
#pragma unroll
    for (int o = 16; o; o >>= 1) v += __shfl_down_sync(0xffffffffu, v, o);
    if ((threadIdx.x & 31) == 0) sh[threadIdx.x >> 5] = v;
    __syncthreads();
    double r = 0.0;
    if (threadIdx.x == 0)
        for (int i = 0; i < 8; i++) r += sh[i];
    __syncthreads();
    return r;  // valid on thread 0
}

__global__ __launch_bounds__(256) void k_regulator(const float* __restrict__ r1w,
                                                   const float* __restrict__ r1b,
                                                   const float* __restrict__ lng,
                                                   const float* __restrict__ lnb,
                                                   const float* __restrict__ r2w,
                                                   const float* __restrict__ r2b) {
    __shared__ double sh[8];
    const int tid = threadIdx.x;
    double a = 0, b = 0, c = 0, d = 0, e = 0;
    for (int i = tid; i < 1024; i += 256) { a += (double)g_px[i]; b += (double)g_pxx[i]; }
    for (int i = tid; i < 512; i += 256)  { c += (double)g_pw[i]; d += (double)g_pf[i]; }
    for (int i = tid; i < 2048; i += 256) { e += (double)g_pabs[i]; }
    a = blockReduce256d(a, sh);
    b = blockReduce256d(b, sh);
    c = blockReduce256d(c, sh);
    d = blockReduce256d(d, sh);
    e = blockReduce256d(e, sh);
    if (tid == 0) {
        const double cnt = (double)NR * (double)DIMN;
        double mean = a / cnt;
        float stress = (float)(b / cnt - mean * mean);
        float excit  = (float)(e / cnt);
        float fatig  = sqrtf((float)c);
        float sig[3] = {stress, excit, fatig};
        float h[16];
        float mu = 0.f;
#pragma unroll
        for (int i = 0; i < 16; i++) {
            h[i] = r1b[i] + sig[0] * r1w[i * 3 + 0] + sig[1] * r1w[i * 3 + 1] + sig[2] * r1w[i * 3 + 2];
            mu += h[i];
        }
        mu *= (1.0f / 16.0f);
        float var = 0.f;
#pragma unroll
        for (int i = 0; i < 16; i++) { float dd = h[i] - mu; var += dd * dd; }
        var *= (1.0f / 16.0f);
        float rstd = rsqrtf(var + LN_EPS);
#pragma unroll
        for (int i = 0; i < 16; i++) h[i] = tanhf((h[i] - mu) * rstd * lng[i] + lnb[i]);
#pragma unroll
        for (int i = 0; i < 3; i++) {
            float s = r2b[i];
#pragma unroll
            for (int j = 0; j < 16; j++) s += h[j] * r2w[i * 16 + j];
            g_ctrl[i] = sigmoidf_(s);
        }
        g_flag = (d > 0.0) ? 1 : 0;
    }
}

// ---------------- general fast-weight path (flag-gated; exact no-op when Wf==0) ------
__global__ __launch_bounds__(256) void k_colsq() {
    if (g_flag == 0) return;
    const int j = blockIdx.x;
    float s = 0.f;
    for (int i = threadIdx.x; i < NR; i += blockDim.x) {
        float t = g_y[(size_t)i * DIMN + j];
        s += t * t;
    }
#pragma unroll
    for (int o = 16; o; o >>= 1) s += __shfl_down_sync(0xffffffffu, s, o);
    __shared__ float sh[8];
    if ((threadIdx.x & 31) == 0) sh[threadIdx.x >> 5] = s;
    __syncthreads();
    if (threadIdx.x == 0) {
        float t = 0.f;
        for (int i = 0; i < 8; i++) t += sh[i];
        g_colsq[j] = t;
    }
}

// hebb = y^T x / n : C[j,k] = (1/n) sum_i y[i,j] x[i,k].  64x64 tiles, BK=16.
__global__ __launch_bounds__(256) void k_hebb(const float* __restrict__ Bx) {
    if (g_flag == 0) return;
    __shared__ float As[16][64];
    __shared__ float Bs[16][64];
    const int tid = threadIdx.x;
    const int m0 = blockIdx.y * 64, n0 = blockIdx.x * 64;
    const int lk = tid >> 4;        // 0..15
    const int lm = (tid & 15) * 4;  // 0..60
    const int tx = tid & 15, ty = tid >> 4;
    float acc[4][4] = {};
    for (int k0 = 0; k0 < NR; k0 += 16) {
        float4 a = *(const float4*)&g_y[(size_t)(k0 + lk) * DIMN + m0 + lm];
        float4 b = *(const float4*)&Bx[(size_t)(k0 + lk) * DIMN + n0 + lm];
        *(float4*)&As[lk][lm] = a;
        *(float4*)&Bs[lk][lm] = b;
        __syncthreads();
#pragma unroll
        for (int k = 0; k < 16; k++) {
            float av[4], bv[4];
#pragma unroll
            for (int i = 0; i < 4; i++) { av[i] = As[k][ty * 4 + i]; bv[i] = Bs[k][tx * 4 + i]; }
#pragma unroll
            for (int i = 0; i < 4; i++)
#pragma unroll
                for (int j = 0; j < 4; j++) acc[i][j] += av[i] * bv[j];
        }
        __syncthreads();
    }
    const float scale = 1.0f / (float)NR;
#pragma unroll
    for (int i = 0; i < 4; i++)
#pragma unroll
        for (int j = 0; j < 4; j++)
            g_hebb[(size_t)(m0 + ty * 4 + i) * DIMN + n0 + tx * 4 + j] = acc[i][j] * scale;
}

__global__ __launch_bounds__(256) void k_wfnew(const float* __restrict__ wf) {
    if (g_flag == 0) return;
    const float rate = g_ctrl[1] * 0.1f;
    const float invn = 1.0f / (float)NR;
    for (size_t idx = (size_t)blockIdx.x * blockDim.x + threadIdx.x;
         idx < (size_t)DIMN * DIMN; idx += (size_t)gridDim.x * blockDim.x) {
        int j = (int)(idx / DIMN);
        float w = wf[idx];
        float forget = g_colsq[j] * invn * w;
        g_wfnew[idx] = w + tanhf(g_hebb[idx] - forget) * rate;
    }
}

// ---------------- fused gate + output epilogue (one block per row) ----------------
__global__ __launch_bounds__(256) void k_finalize(const float* __restrict__ gw,
                                                  const float* __restrict__ gb,
                                                  float* __restrict__ out) {
    __shared__ float row[DIMN];
    __shared__ float red[8];
    __shared__ float s_gate;
    const int r = blockIdx.x;
    const float4* vrow = (const float4*)(g_v + (size_t)r * DIMN);
    const float4* gw4 = (const float4*)gw;
    float p = 0.f;
    for (int i = threadIdx.x; i < DIMN / 4; i += 256) {
        float4 t = vrow[i];
        float4 g = gw4[i];
        ((float4*)row)[i] = t;
        p += t.x * g.x + t.y * g.y + t.z * g.z + t.w * g.w;
    }
#pragma unroll
    for (int o = 16; o; o >>= 1) p += __shfl_down_sync(0xffffffffu, p, o);
    if ((threadIdx.x & 31) == 0) red[threadIdx.x >> 5] = p;
    __syncthreads();
    if (threadIdx.x == 0) {
        float s = 0.f;
        for (int i = 0; i < 8; i++) s += red[i];
        s_gate = g_ctrl[0] * sigmoidf_(s + gb[0]);
    }
    __syncthreads();
    const float gate = s_gate;
    const int flag = g_flag;
    const float c2 = g_ctrl[2];
    float4* o4 = (float4*)(out + (size_t)r * DIMN);
    const float4* f4 = (const float4*)(g_fast + (size_t)r * DIMN);
    for (int i = threadIdx.x; i < DIMN / 4; i += 256) {
        float4 t = ((float4*)row)[i];
        if (flag) {
            float4 f = f4[i];
            t.x += f.x * c2; t.y += f.y * c2; t.z += f.z * c2; t.w += f.w * c2;
        }
        t.x *= gate; t.y *= gate; t.z *= gate; t.w *= gate;
        o4[i] = t;
    }
}

// ---------------- launch ----------------
extern "C" void kernel_launch(void* const* d_in, const int* in_sizes, int n_in,
                              void* d_out, int out_size) {
    const float* x     = (const float*)d_in[0];
    const float* Vw    = (const float*)d_in[1];
    const float* Wslow = (const float*)d_in[2];
    const float* gw    = (const float*)d_in[3];
    const float* gb    = (const float*)d_in[4];
    const float* r1w   = (const float*)d_in[5];
    const float* r1b   = (const float*)d_in[6];
    const float* lng   = (const float*)d_in[7];
    const float* lnb   = (const float*)d_in[8];
    const float* r2w   = (const float*)d_in[9];
    const float* r2b   = (const float*)d_in[10];
    const float* Wfast = (const float*)d_in[11];
    float* out = (float*)d_out;

    float *pv, *py, *pfast, *pwfnew;
    cudaGetSymbolAddress((void**)&pv, g_v);
    cudaGetSymbolAddress((void**)&py, g_y);
    cudaGetSymbolAddress((void**)&pfast, g_fast);
    cudaGetSymbolAddress((void**)&pwfnew, g_wfnew);

    k_stats_x<<<1024, 256>>>((const float4*)x, NR * DIMN / 4);
    k_stats_w<<<512, 256>>>((const float4*)Wslow, (const float4*)Wfast, DIMN * DIMN / 4);

    dim3 gv(DIMN / 128, NR / 128);
    sgemm_nt<true, false><<<gv, 256>>>(x, Vw, pv, NR, DIMN, DIMN);

    k_regulator<<<1, 256>>>(r1w, r1b, lng, lnb, r2w, r2b);

    // General fast-weight path; every kernel early-exits when W_fast == 0
    // (then y=0, hebb=0, forget=0, Wf_new=0, fast_out=0 exactly).
    sgemm_nt<false, true><<<gv, 256>>>(x, Wfast, py, NR, DIMN, DIMN);
    k_colsq<<<DIMN, 256>>>();
    dim3 gh(DIMN / 64, DIMN / 64);
    k_hebb<<<gh, 256>>>(x);
    k_wfnew<<<4096, 256>>>(Wfast);
    sgemm_nt<false, true><<<gv, 256>>>(x, pwfnew, pfast, NR, DIMN, DIMN);

    k_finalize<<<NR, 256>>>(gw, gb, out);
}

// round 4
// speedup vs baseline: 1.8705x; 1.8705x over previous
#include <cuda_runtime.h>
#include <cuda_bf16.h>
#include <math.h>
#include <stdint.h>

#define DIMN 2048
#define NR   16384
#define LN_EPS 1e-5f

// ============================ scratch (device globals) ============================
__device__ float g_v[(size_t)NR * DIMN];
__device__ float g_y[(size_t)NR * DIMN];
__device__ float g_fast[(size_t)NR * DIMN];
__device__ float g_hebb[(size_t)DIMN * DIMN];
__device__ float g_wfnew[(size_t)DIMN * DIMN];
__device__ float g_colsq[DIMN];
__device__ float g_px[1024];
__device__ float g_pxx[1024];
__device__ float g_pw[512];
__device__ int   g_pf[512];
__device__ float g_pabs[2048];   // one partial per GEMM CTA (16 x 128 grid)
__device__ float g_ctrl[3];
__device__ int   g_flag;

__device__ __forceinline__ float sigmoidf_(float x) { return 1.0f / (1.0f + expf(-x)); }

__device__ __forceinline__ uint32_t f2tf32(float f) {
    uint32_t r;
    asm("cvt.rna.tf32.f32 %0, %1;" : "=r"(r) : "f"(f));
    return r;
}

__device__ __forceinline__ void mma_tf32(float c[4], const uint32_t a[4], const uint32_t b[2]) {
    asm volatile(
        "mma.sync.aligned.m16n8k8.row.col.f32.tf32.tf32.f32 "
        "{%0,%1,%2,%3}, {%4,%5,%6,%7}, {%8,%9}, {%0,%1,%2,%3};"
        : "+f"(c[0]), "+f"(c[1]), "+f"(c[2]), "+f"(c[3])
        : "r"(a[0]), "r"(a[1]), "r"(a[2]), "r"(a[3]), "r"(b[0]), "r"(b[1]));
}

// ============================ stats ============================
__global__ __launch_bounds__(256) void k_stats_x(const float4* __restrict__ x, int n4) {
    float s = 0.f, s2 = 0.f;
    for (int i = blockIdx.x * blockDim.x + threadIdx.x; i < n4; i += gridDim.x * blockDim.x) {
        float4 t = x[i];
        s  += t.x + t.y + t.z + t.w;
        s2 += t.x * t.x + t.y * t.y + t.z * t.z + t.w * t.w;
    }
#pragma unroll
    for (int o = 16; o; o >>= 1) {
        s  += __shfl_down_sync(0xffffffffu, s, o);
        s2 += __shfl_down_sync(0xffffffffu, s2, o);
    }
    __shared__ float sh1[8], sh2[8];
    if ((threadIdx.x & 31) == 0) { sh1[threadIdx.x >> 5] = s; sh2[threadIdx.x >> 5] = s2; }
    __syncthreads();
    if (threadIdx.x == 0) {
        float a = 0.f, b = 0.f;
        for (int i = 0; i < 8; i++) { a += sh1[i]; b += sh2[i]; }
        g_px[blockIdx.x] = a;
        g_pxx[blockIdx.x] = b;
    }
}

__global__ __launch_bounds__(256) void k_stats_w(const float4* __restrict__ ws,
                                                 const float4* __restrict__ wf, int n4) {
    float s2 = 0.f;
    int cnt = 0;
    for (int i = blockIdx.x * blockDim.x + threadIdx.x; i < n4; i += gridDim.x * blockDim.x) {
        float4 a = ws[i];
        s2 += a.x * a.x + a.y * a.y + a.z * a.z + a.w * a.w;
        float4 b = wf[i];
        cnt += (b.x != 0.f) + (b.y != 0.f) + (b.z != 0.f) + (b.w != 0.f);
    }
#pragma unroll
    for (int o = 16; o; o >>= 1) {
        s2  += __shfl_down_sync(0xffffffffu, s2, o);
        cnt += __shfl_down_sync(0xffffffffu, cnt, o);
    }
    __shared__ float sh1[8];
    __shared__ int   sh2[8];
    if ((threadIdx.x & 31) == 0) { sh1[threadIdx.x >> 5] = s2; sh2[threadIdx.x >> 5] = cnt; }
    __syncthreads();
    if (threadIdx.x == 0) {
        float a = 0.f; int b = 0;
        for (int i = 0; i < 8; i++) { a += sh1[i]; b += sh2[i]; }
        g_pw[blockIdx.x] = a;
        g_pf[blockIdx.x] = b;
    }
}

// ============================ tf32 mma.sync GEMM: v = x @ V^T ============================
// C[M=16384, N=2048] = A[M,K=2048] @ B[N,K]^T, both K-major.
// CTA tile 128x128, 8 warps (2 x 4), warp tile 64x32, K-chunk 32.
// SMEM: tf32-converted tiles, row stride 36 words (conflict-free frag loads).
// Double buffered, reg-staged global loads, cvt.rna at STS time.
#define GKC 32
#define NCHUNKS (DIMN / GKC)       // 64
#define LDS_STRIDE 36
#define TILE_WORDS (128 * LDS_STRIDE)   // 4608
#define SMEM_GEMM_BYTES (4 * TILE_WORDS * 4)  // A0,A1,B0,B1 = 73728

__global__ void __launch_bounds__(256, 1) k_gemm_v(const float* __restrict__ A,
                                                   const float* __restrict__ B,
                                                   float* __restrict__ C) {
    extern __shared__ uint32_t sm[];
    __shared__ float s_red[8];
    const int tid = threadIdx.x;
    const int wid = tid >> 5;
    const int lane = tid & 31;
    const int gid = lane >> 2;        // 0..7
    const int tig = lane & 3;         // 0..3
    const int m0 = blockIdx.y * 128;
    const int n0 = blockIdx.x * 128;
    const int wm0 = (wid & 1) * 64;   // warp row offset in tile
    const int wn0 = (wid >> 1) * 32;  // warp col offset in tile

    float4 pa[4], pb[4];
    // 4 staged float4 loads per operand: idx = tid + j*256; row = idx>>3, c = idx&7
#pragma unroll
    for (int j = 0; j < 4; j++) {
        int idx = tid + j * 256;
        int row = idx >> 3, c = idx & 7;
        pa[j] = *(const float4*)(A + (size_t)(m0 + row) * DIMN + c * 4);
        pb[j] = *(const float4*)(B + (size_t)(n0 + row) * DIMN + c * 4);
    }
    // convert + store chunk 0 into buffer 0
    {
        uint32_t* As = sm;
        uint32_t* Bs = sm + 2 * TILE_WORDS;
#pragma unroll
        for (int j = 0; j < 4; j++) {
            int idx = tid + j * 256;
            int row = idx >> 3, c = idx & 7;
            uint4 ua = make_uint4(f2tf32(pa[j].x), f2tf32(pa[j].y), f2tf32(pa[j].z), f2tf32(pa[j].w));
            uint4 ub = make_uint4(f2tf32(pb[j].x), f2tf32(pb[j].y), f2tf32(pb[j].z), f2tf32(pb[j].w));
            *(uint4*)(As + row * LDS_STRIDE + c * 4) = ua;
            *(uint4*)(Bs + row * LDS_STRIDE + c * 4) = ub;
        }
    }
    __syncthreads();

    float acc[4][4][4];
#pragma unroll
    for (int mt = 0; mt < 4; mt++)
#pragma unroll
        for (int nt = 0; nt < 4; nt++)
#pragma unroll
            for (int r = 0; r < 4; r++) acc[mt][nt][r] = 0.f;

#pragma unroll 1
    for (int t = 0; t < NCHUNKS; ++t) {
        // prefetch next chunk to regs
        if (t + 1 < NCHUNKS) {
            const int k0 = (t + 1) * GKC;
#pragma unroll
            for (int j = 0; j < 4; j++) {
                int idx = tid + j * 256;
                int row = idx >> 3, c = idx & 7;
                pa[j] = *(const float4*)(A + (size_t)(m0 + row) * DIMN + k0 + c * 4);
                pb[j] = *(const float4*)(B + (size_t)(n0 + row) * DIMN + k0 + c * 4);
            }
        }
        // compute chunk t
        {
            const uint32_t* As = sm + (t & 1) * TILE_WORDS;
            const uint32_t* Bs = sm + 2 * TILE_WORDS + (t & 1) * TILE_WORDS;
#pragma unroll
            for (int s = 0; s < 4; s++) {
                const int kb = s * 8;
                uint32_t af[4][4];
#pragma unroll
                for (int mt = 0; mt < 4; mt++) {
                    const int rb = wm0 + mt * 16;
                    af[mt][0] = As[(rb + gid) * LDS_STRIDE + kb + tig];
                    af[mt][1] = As[(rb + gid + 8) * LDS_STRIDE + kb + tig];
                    af[mt][2] = As[(rb + gid) * LDS_STRIDE + kb + tig + 4];
                    af[mt][3] = As[(rb + gid + 8) * LDS_STRIDE + kb + tig + 4];
                }
                uint32_t bf[4][2];
#pragma unroll
                for (int nt = 0; nt < 4; nt++) {
                    const int cb = wn0 + nt * 8;
                    bf[nt][0] = Bs[(cb + gid) * LDS_STRIDE + kb + tig];
                    bf[nt][1] = Bs[(cb + gid) * LDS_STRIDE + kb + tig + 4];
                }
#pragma unroll
                for (int mt = 0; mt < 4; mt++)
#pragma unroll
                    for (int nt = 0; nt < 4; nt++) mma_tf32(acc[mt][nt], af[mt], bf[nt]);
            }
        }
        // convert + store next chunk
        if (t + 1 < NCHUNKS) {
            uint32_t* As = sm + ((t + 1) & 1) * TILE_WORDS;
            uint32_t* Bs = sm + 2 * TILE_WORDS + ((t + 1) & 1) * TILE_WORDS;
#pragma unroll
            for (int j = 0; j < 4; j++) {
                int idx = tid + j * 256;
                int row = idx >> 3, c = idx & 7;
                uint4 ua = make_uint4(f2tf32(pa[j].x), f2tf32(pa[j].y), f2tf32(pa[j].z), f2tf32(pa[j].w));
                uint4 ub = make_uint4(f2tf32(pb[j].x), f2tf32(pb[j].y), f2tf32(pb[j].z), f2tf32(pb[j].w));
                *(uint4*)(As + row * LDS_STRIDE + c * 4) = ua;
                *(uint4*)(Bs + row * LDS_STRIDE + c * 4) = ub;
            }
        }
        __syncthreads();
    }

    // epilogue: write C + |v| partial
    float asum = 0.f;
#pragma unroll
    for (int mt = 0; mt < 4; mt++) {
        const int r0 = m0 + wm0 + mt * 16 + gid;
        const int r1 = r0 + 8;
#pragma unroll
        for (int nt = 0; nt < 4; nt++) {
            const int cc = n0 + wn0 + nt * 8 + tig * 2;
            float c0 = acc[mt][nt][0], c1 = acc[mt][nt][1];
            float c2 = acc[mt][nt][2], c3 = acc[mt][nt][3];
            *(float2*)(C + (size_t)r0 * DIMN + cc) = make_float2(c0, c1);
            *(float2*)(C + (size_t)r1 * DIMN + cc) = make_float2(c2, c3);
            asum += fabsf(c0) + fabsf(c1) + fabsf(c2) + fabsf(c3);
        }
    }
#pragma unroll
    for (int o = 16; o; o >>= 1) asum += __shfl_down_sync(0xffffffffu, asum, o);
    if (lane == 0) s_red[wid] = asum;
    __syncthreads();
    if (tid == 0) {
        float s = 0.f;
        for (int i = 0; i < 8; i++) s += s_red[i];
        g_pabs[blockIdx.y * gridDim.x + blockIdx.x] = s;
    }
}

// ============================ regulator ============================
__device__ __forceinline__ double blockReduce256d(double v, double* sh) {
#pragma unroll
    for (int o = 16; o; o >>= 1) v += __shfl_down_sync(0xffffffffu, v, o);
    if ((threadIdx.x & 31) == 0) sh[threadIdx.x >> 5] = v;
    __syncthreads();
    double r = 0.0;
    if (threadIdx.x == 0)
        for (int i = 0; i < 8; i++) r += sh[i];
    __syncthreads();
    return r;
}

__global__ __launch_bounds__(256) void k_regulator(const float* __restrict__ r1w,
                                                   const float* __restrict__ r1b,
                                                   const float* __restrict__ lng,
                                                   const float* __restrict__ lnb,
                                                   const float* __restrict__ r2w,
                                                   const float* __restrict__ r2b) {
    __shared__ double sh[8];
    const int tid = threadIdx.x;
    double a = 0, b = 0, c = 0, d = 0, e = 0;
    for (int i = tid; i < 1024; i += 256) { a += (double)g_px[i]; b += (double)g_pxx[i]; }
    for (int i = tid; i < 512; i += 256)  { c += (double)g_pw[i]; d += (double)g_pf[i]; }
    for (int i = tid; i < 2048; i += 256) { e += (double)g_pabs[i]; }
    a = blockReduce256d(a, sh);
    b = blockReduce256d(b, sh);
    c = blockReduce256d(c, sh);
    d = blockReduce256d(d, sh);
    e = blockReduce256d(e, sh);
    if (tid == 0) {
        const double cnt = (double)NR * (double)DIMN;
        double mean = a / cnt;
        float stress = (float)(b / cnt - mean * mean);
        float excit  = (float)(e / cnt);
        float fatig  = sqrtf((float)c);
        float sig[3] = {stress, excit, fatig};
        float h[16];
        float mu = 0.f;
#pragma unroll
        for (int i = 0; i < 16; i++) {
            h[i] = r1b[i] + sig[0] * r1w[i * 3 + 0] + sig[1] * r1w[i * 3 + 1] + sig[2] * r1w[i * 3 + 2];
            mu += h[i];
        }
        mu *= (1.0f / 16.0f);
        float var = 0.f;
#pragma unroll
        for (int i = 0; i < 16; i++) { float dd = h[i] - mu; var += dd * dd; }
        var *= (1.0f / 16.0f);
        float rstd = rsqrtf(var + LN_EPS);
#pragma unroll
        for (int i = 0; i < 16; i++) h[i] = tanhf((h[i] - mu) * rstd * lng[i] + lnb[i]);
#pragma unroll
        for (int i = 0; i < 3; i++) {
            float s = r2b[i];
#pragma unroll
            for (int j = 0; j < 16; j++) s += h[j] * r2w[i * 16 + j];
            g_ctrl[i] = sigmoidf_(s);
        }
        g_flag = (d > 0.0) ? 1 : 0;
    }
}

// ============================ flag-gated general fast-weight path ============================
__global__ __launch_bounds__(256, 2) void sgemm_nt_flag(const float* __restrict__ A,
                                                        const float* __restrict__ B,
                                                        float* __restrict__ C,
                                                        int M, int N, int K) {
    if (g_flag == 0) return;
    constexpr int BM = 128, BN = 128, BK = 8;
    __shared__ float As[2][BK][BM];
    __shared__ float Bs[2][BK][BN];
    const int tid = threadIdx.x;
    const int m0 = blockIdx.y * BM;
    const int n0 = blockIdx.x * BN;
    const int lr = tid >> 1;
    const int lc = (tid & 1) * 4;
    const int tx = tid & 15;
    const int ty = tid >> 4;
    const float* Aptr = A + (size_t)(m0 + lr) * K + lc;
    const float* Bptr = B + (size_t)(n0 + lr) * K + lc;
    float acc[8][8] = {};
    float4 pa = *(const float4*)Aptr;
    float4 pb = *(const float4*)Bptr;
    As[0][lc + 0][lr] = pa.x; As[0][lc + 1][lr] = pa.y; As[0][lc + 2][lr] = pa.z; As[0][lc + 3][lr] = pa.w;
    Bs[0][lc + 0][lr] = pb.x; Bs[0][lc + 1][lr] = pb.y; Bs[0][lc + 2][lr] = pb.z; Bs[0][lc + 3][lr] = pb.w;
    __syncthreads();
    const int T = K / BK;
    int buf = 0;
    for (int t = 0; t < T; ++t) {
        const bool has = (t + 1 < T);
        if (has) {
            pa = *(const float4*)(Aptr + (t + 1) * BK);
            pb = *(const float4*)(Bptr + (t + 1) * BK);
        }
#pragma unroll
        for (int k = 0; k < BK; ++k) {
            float4 a0 = *(const float4*)&As[buf][k][ty * 8];
            float4 a1 = *(const float4*)&As[buf][k][ty * 8 + 4];
            float4 b0 = *(const float4*)&Bs[buf][k][tx * 8];
            float4 b1 = *(const float4*)&Bs[buf][k][tx * 8 + 4];
            float av[8] = {a0.x, a0.y, a0.z, a0.w, a1.x, a1.y, a1.z, a1.w};
            float bv[8] = {b0.x, b0.y, b0.z, b0.w, b1.x, b1.y, b1.z, b1.w};
#pragma unroll
            for (int i = 0; i < 8; i++)
#pragma unroll
                for (int j = 0; j < 8; j++) acc[i][j] += av[i] * bv[j];
        }
        if (has) {
            int w = buf ^ 1;
            As[w][lc + 0][lr] = pa.x; As[w][lc + 1][lr] = pa.y; As[w][lc + 2][lr] = pa.z; As[w][lc + 3][lr] = pa.w;
            Bs[w][lc + 0][lr] = pb.x; Bs[w][lc + 1][lr] = pb.y; Bs[w][lc + 2][lr] = pb.z; Bs[w][lc + 3][lr] = pb.w;
            __syncthreads();
            buf = w;
        }
    }
#pragma unroll
    for (int i = 0; i < 8; i++) {
        size_t off = (size_t)(m0 + ty * 8 + i) * N + n0 + tx * 8;
        *(float4*)&C[off]     = make_float4(acc[i][0], acc[i][1], acc[i][2], acc[i][3]);
        *(float4*)&C[off + 4] = make_float4(acc[i][4], acc[i][5], acc[i][6], acc[i][7]);
    }
}

__global__ __launch_bounds__(256) void k_colsq() {
    if (g_flag == 0) return;
    const int j = blockIdx.x;
    float s = 0.f;
    for (int i = threadIdx.x; i < NR; i += blockDim.x) {
        float t = g_y[(size_t)i * DIMN + j];
        s += t * t;
    }
#pragma unroll
    for (int o = 16; o; o >>= 1) s += __shfl_down_sync(0xffffffffu, s, o);
    __shared__ float sh[8];
    if ((threadIdx.x & 31) == 0) sh[threadIdx.x >> 5] = s;
    __syncthreads();
    if (threadIdx.x == 0) {
        float t = 0.f;
        for (int i = 0; i < 8; i++) t += sh[i];
        g_colsq[j] = t;
    }
}

__global__ __launch_bounds__(256) void k_hebb(const float* __restrict__ Bx) {
    if (g_flag == 0) return;
    __shared__ float As[16][64];
    __shared__ float Bs[16][64];
    const int tid = threadIdx.x;
    const int m0 = blockIdx.y * 64, n0 = blockIdx.x * 64;
    const int lk = tid >> 4;
    const int lm = (tid & 15) * 4;
    const int tx = tid & 15, ty = tid >> 4;
    float acc[4][4] = {};
    for (int k0 = 0; k0 < NR; k0 += 16) {
        float4 a = *(const float4*)&g_y[(size_t)(k0 + lk) * DIMN + m0 + lm];
        float4 b = *(const float4*)&Bx[(size_t)(k0 + lk) * DIMN + n0 + lm];
        *(float4*)&As[lk][lm] = a;
        *(float4*)&Bs[lk][lm] = b;
        __syncthreads();
#pragma unroll
        for (int k = 0; k < 16; k++) {
            float av[4], bv[4];
#pragma unroll
            for (int i = 0; i < 4; i++) { av[i] = As[k][ty * 4 + i]; bv[i] = Bs[k][tx * 4 + i]; }
#pragma unroll
            for (int i = 0; i < 4; i++)
#pragma unroll
                for (int j = 0; j < 4; j++) acc[i][j] += av[i] * bv[j];
        }
        __syncthreads();
    }
    const float scale = 1.0f / (float)NR;
#pragma unroll
    for (int i = 0; i < 4; i++)
#pragma unroll
        for (int j = 0; j < 4; j++)
            g_hebb[(size_t)(m0 + ty * 4 + i) * DIMN + n0 + tx * 4 + j] = acc[i][j] * scale;
}

__global__ __launch_bounds__(256) void k_wfnew(const float* __restrict__ wf) {
    if (g_flag == 0) return;
    const float rate = g_ctrl[1] * 0.1f;
    const float invn = 1.0f / (float)NR;
    for (size_t idx = (size_t)blockIdx.x * blockDim.x + threadIdx.x;
         idx < (size_t)DIMN * DIMN; idx += (size_t)gridDim.x * blockDim.x) {
        int j = (int)(idx / DIMN);
        float w = wf[idx];
        float forget = g_colsq[j] * invn * w;
        g_wfnew[idx] = w + tanhf(g_hebb[idx] - forget) * rate;
    }
}

// ============================ fused gate + epilogue ============================
__global__ __launch_bounds__(256) void k_finalize(const float* __restrict__ gw,
                                                  const float* __restrict__ gb,
                                                  float* __restrict__ out) {
    __shared__ float row[DIMN];
    __shared__ float red[8];
    __shared__ float s_gate;
    const int r = blockIdx.x;
    const float4* vrow = (const float4*)(g_v + (size_t)r * DIMN);
    const float4* gw4 = (const float4*)gw;
    float p = 0.f;
    for (int i = threadIdx.x; i < DIMN / 4; i += 256) {
        float4 t = vrow[i];
        float4 g = gw4[i];
        ((float4*)row)[i] = t;
        p += t.x * g.x + t.y * g.y + t.z * g.z + t.w * g.w;
    }
#pragma unroll
    for (int o = 16; o; o >>= 1) p += __shfl_down_sync(0xffffffffu, p, o);
    if ((threadIdx.x & 31) == 0) red[threadIdx.x >> 5] = p;
    __syncthreads();
    if (threadIdx.x == 0) {
        float s = 0.f;
        for (int i = 0; i < 8; i++) s += red[i];
        s_gate = g_ctrl[0] * sigmoidf_(s + gb[0]);
    }
    __syncthreads();
    const float gate = s_gate;
    const int flag = g_flag;
    const float c2 = g_ctrl[2];
    float4* o4 = (float4*)(out + (size_t)r * DIMN);
    const float4* f4 = (const float4*)(g_fast + (size_t)r * DIMN);
    for (int i = threadIdx.x; i < DIMN / 4; i += 256) {
        float4 t = ((float4*)row)[i];
        if (flag) {
            float4 f = f4[i];
            t.x += f.x * c2; t.y += f.y * c2; t.z += f.z * c2; t.w += f.w * c2;
        }
        t.x *= gate; t.y *= gate; t.z *= gate; t.w *= gate;
        o4[i] = t;
    }
}

// ============================ launch ============================
extern "C" void kernel_launch(void* const* d_in, const int* in_sizes, int n_in,
                              void* d_out, int out_size) {
    const float* x     = (const float*)d_in[0];
    const float* Vw    = (const float*)d_in[1];
    const float* Wslow = (const float*)d_in[2];
    const float* gw    = (const float*)d_in[3];
    const float* gb    = (const float*)d_in[4];
    const float* r1w   = (const float*)d_in[5];
    const float* r1b   = (const float*)d_in[6];
    const float* lng   = (const float*)d_in[7];
    const float* lnb   = (const float*)d_in[8];
    const float* r2w   = (const float*)d_in[9];
    const float* r2b   = (const float*)d_in[10];
    const float* Wfast = (const float*)d_in[11];
    float* out = (float*)d_out;

    float *pv, *py, *pfast, *pwfnew;
    cudaGetSymbolAddress((void**)&pv, g_v);
    cudaGetSymbolAddress((void**)&py, g_y);
    cudaGetSymbolAddress((void**)&pfast, g_fast);
    cudaGetSymbolAddress((void**)&pwfnew, g_wfnew);

    cudaFuncSetAttribute(k_gemm_v, cudaFuncAttributeMaxDynamicSharedMemorySize, SMEM_GEMM_BYTES);

    k_stats_x<<<1024, 256>>>((const float4*)x, NR * DIMN / 4);
    k_stats_w<<<512, 256>>>((const float4*)Wslow, (const float4*)Wfast, DIMN * DIMN / 4);

    dim3 gg(DIMN / 128, NR / 128);   // (16, 128) -> 2048 CTAs
    k_gemm_v<<<gg, 256, SMEM_GEMM_BYTES>>>(x, Vw, pv);

    k_regulator<<<1, 256>>>(r1w, r1b, lng, lnb, r2w, r2b);

    // general fast-weight path; every kernel early-exits when W_fast == 0
    dim3 gv(DIMN / 128, NR / 128);
    sgemm_nt_flag<<<gv, 256>>>(x, Wfast, py, NR, DIMN, DIMN);
    k_colsq<<<DIMN, 256>>>();
    dim3 gh(DIMN / 64, DIMN / 64);
    k_hebb<<<gh, 256>>>(x);
    k_wfnew<<<4096, 256>>>(Wfast);
    sgemm_nt_flag<<<gv, 256>>>(x, pwfnew, pfast, NR, DIMN, DIMN);

    k_finalize<<<NR, 256>>>(gw, gb, out);
}

// round 7
// speedup vs baseline: 2.5857x; 1.3824x over previous
#include <cuda_runtime.h>
#include <cuda_bf16.h>
#include <math.h>
#include <stdint.h>

#define DIMN 2048
#define NR   16384
#define LN_EPS 1e-5f

// ============================ scratch (device globals) ============================
__device__ float g_v[(size_t)NR * DIMN];
__device__ float g_y[(size_t)NR * DIMN];
__device__ float g_fast[(size_t)NR * DIMN];
__device__ float g_hebb[(size_t)DIMN * DIMN];
__device__ float g_wfnew[(size_t)DIMN * DIMN];
__device__ float g_colsq[DIMN];
__device__ float g_px[1024];
__device__ float g_pxx[1024];
__device__ float g_pw[512];
__device__ int   g_pf[512];
__device__ float g_pabs[2048];   // one partial per GEMM CTA (16 x 128 grid)
__device__ float g_ctrl[3];
__device__ int   g_flag;

__device__ __forceinline__ float sigmoidf_(float x) { return 1.0f / (1.0f + expf(-x)); }

__device__ __forceinline__ uint32_t f2tf32(float f) {
    uint32_t r;
    asm("cvt.rna.tf32.f32 %0, %1;" : "=r"(r) : "f"(f));
    return r;
}

__device__ __forceinline__ void mma_tf32(float c[4], const uint32_t a[4], const uint32_t b[2]) {
    asm volatile(
        "mma.sync.aligned.m16n8k8.row.col.f32.tf32.tf32.f32 "
        "{%0,%1,%2,%3}, {%4,%5,%6,%7}, {%8,%9}, {%0,%1,%2,%3};"
        : "+f"(c[0]), "+f"(c[1]), "+f"(c[2]), "+f"(c[3])
        : "r"(a[0]), "r"(a[1]), "r"(a[2]), "r"(a[3]), "r"(b[0]), "r"(b[1]));
}

// ============================ stats ============================
__global__ __launch_bounds__(256) void k_stats_x(const float4* __restrict__ x, int n4) {
    float s = 0.f, s2 = 0.f;
    for (int i = blockIdx.x * blockDim.x + threadIdx.x; i < n4; i += gridDim.x * blockDim.x) {
        float4 t = x[i];
        s  += t.x + t.y + t.z + t.w;
        s2 += t.x * t.x + t.y * t.y + t.z * t.z + t.w * t.w;
    }
#pragma unroll
    for (int o = 16; o; o >>= 1) {
        s  += __shfl_down_sync(0xffffffffu, s, o);
        s2 += __shfl_down_sync(0xffffffffu, s2, o);
    }
    __shared__ float sh1[8], sh2[8];
    if ((threadIdx.x & 31) == 0) { sh1[threadIdx.x >> 5] = s; sh2[threadIdx.x >> 5] = s2; }
    __syncthreads();
    if (threadIdx.x == 0) {
        float a = 0.f, b = 0.f;
        for (int i = 0; i < 8; i++) { a += sh1[i]; b += sh2[i]; }
        g_px[blockIdx.x] = a;
        g_pxx[blockIdx.x] = b;
    }
}

__global__ __launch_bounds__(256) void k_stats_w(const float4* __restrict__ ws,
                                                 const float4* __restrict__ wf, int n4) {
    float s2 = 0.f;
    int cnt = 0;
    for (int i = blockIdx.x * blockDim.x + threadIdx.x; i < n4; i += gridDim.x * blockDim.x) {
        float4 a = ws[i];
        s2 += a.x * a.x + a.y * a.y + a.z * a.z + a.w * a.w;
        float4 b = wf[i];
        cnt += (b.x != 0.f) + (b.y != 0.f) + (b.z != 0.f) + (b.w != 0.f);
    }
#pragma unroll
    for (int o = 16; o; o >>= 1) {
        s2  += __shfl_down_sync(0xffffffffu, s2, o);
        cnt += __shfl_down_sync(0xffffffffu, cnt, o);
    }
    __shared__ float sh1[8];
    __shared__ int   sh2[8];
    if ((threadIdx.x & 31) == 0) { sh1[threadIdx.x >> 5] = s2; sh2[threadIdx.x >> 5] = cnt; }
    __syncthreads();
    if (threadIdx.x == 0) {
        float a = 0.f; int b = 0;
        for (int i = 0; i < 8; i++) { a += sh1[i]; b += sh2[i]; }
        g_pw[blockIdx.x] = a;
        g_pf[blockIdx.x] = b;
    }
}

// ============================ tf32 mma.sync GEMM: v = x @ V^T ============================
// C[M,N] = A[M,K] @ B[N,K]^T, K-major. CTA tile 128x128, 256 threads (8 warps),
// warp tile 64x32, K-chunk 16, 2 CTAs/SM (40KB smem, <=128 regs).
// SMEM row stride 20 words: fragment loads conflict-free; cvt.rna at STS time.
#define GKC 16
#define NCHUNKS (DIMN / GKC)            // 128
#define LDS_STRIDE 20
#define TILE_WORDS (128 * LDS_STRIDE)   // 2560
#define SMEM_GEMM_BYTES (4 * TILE_WORDS * 4)  // A0,A1,B0,B1 = 40960

__global__ void __launch_bounds__(256, 2) k_gemm_v(const float* __restrict__ A,
                                                   const float* __restrict__ B,
                                                   float* __restrict__ C) {
    extern __shared__ uint32_t sm[];
    __shared__ float s_red[8];
    const int tid = threadIdx.x;
    const int wid = tid >> 5;
    const int lane = tid & 31;
    const int gid = lane >> 2;        // 0..7
    const int tig = lane & 3;         // 0..3
    const int m0 = blockIdx.y * 128;
    const int n0 = blockIdx.x * 128;
    const int wm0 = (wid & 1) * 64;   // warp row offset in tile
    const int wn0 = (wid >> 1) * 32;  // warp col offset in tile

    // staged loads: each operand tile is 128 rows x 16 cols = 512 float4; 2/thread.
    // idx = tid + j*256; row = idx>>2 (4 float4 per row), c = idx&3.
    float4 pa[2], pb[2];
#pragma unroll
    for (int j = 0; j < 2; j++) {
        int idx = tid + j * 256;
        int row = idx >> 2, c = idx & 3;
        pa[j] = *(const float4*)(A + (size_t)(m0 + row) * DIMN + c * 4);
        pb[j] = *(const float4*)(B + (size_t)(n0 + row) * DIMN + c * 4);
    }
    // convert + store chunk 0 into buffer 0
    {
        uint32_t* As = sm;
        uint32_t* Bs = sm + 2 * TILE_WORDS;
#pragma unroll
        for (int j = 0; j < 2; j++) {
            int idx = tid + j * 256;
            int row = idx >> 2, c = idx & 3;
            uint4 ua = make_uint4(f2tf32(pa[j].x), f2tf32(pa[j].y), f2tf32(pa[j].z), f2tf32(pa[j].w));
            uint4 ub = make_uint4(f2tf32(pb[j].x), f2tf32(pb[j].y), f2tf32(pb[j].z), f2tf32(pb[j].w));
            *(uint4*)(As + row * LDS_STRIDE + c * 4) = ua;
            *(uint4*)(Bs + row * LDS_STRIDE + c * 4) = ub;
        }
    }
    __syncthreads();

    float acc[4][4][4];
#pragma unroll
    for (int mt = 0; mt < 4; mt++)
#pragma unroll
        for (int nt = 0; nt < 4; nt++)
#pragma unroll
            for (int r = 0; r < 4; r++) acc[mt][nt][r] = 0.f;

#pragma unroll 1
    for (int t = 0; t < NCHUNKS; ++t) {
        // prefetch next chunk to regs
        if (t + 1 < NCHUNKS) {
            const int k0 = (t + 1) * GKC;
#pragma unroll
            for (int j = 0; j < 2; j++) {
                int idx = tid + j * 256;
                int row = idx >> 2, c = idx & 3;
                pa[j] = *(const float4*)(A + (size_t)(m0 + row) * DIMN + k0 + c * 4);
                pb[j] = *(const float4*)(B + (size_t)(n0 + row) * DIMN + k0 + c * 4);
            }
        }
        // compute chunk t
        {
            const uint32_t* As = sm + (t & 1) * TILE_WORDS;
            const uint32_t* Bs = sm + 2 * TILE_WORDS + (t & 1) * TILE_WORDS;
#pragma unroll
            for (int s = 0; s < 2; s++) {
                const int kb = s * 8;
                uint32_t af[4][4];
#pragma unroll
                for (int mt = 0; mt < 4; mt++) {
                    const int rb = wm0 + mt * 16;
                    af[mt][0] = As[(rb + gid) * LDS_STRIDE + kb + tig];
                    af[mt][1] = As[(rb + gid + 8) * LDS_STRIDE + kb + tig];
                    af[mt][2] = As[(rb + gid) * LDS_STRIDE + kb + tig + 4];
                    af[mt][3] = As[(rb + gid + 8) * LDS_STRIDE + kb + tig + 4];
                }
                uint32_t bf[4][2];
#pragma unroll
                for (int nt = 0; nt < 4; nt++) {
                    const int cb = wn0 + nt * 8;
                    bf[nt][0] = Bs[(cb + gid) * LDS_STRIDE + kb + tig];
                    bf[nt][1] = Bs[(cb + gid) * LDS_STRIDE + kb + tig + 4];
                }
#pragma unroll
                for (int mt = 0; mt < 4; mt++)
#pragma unroll
                    for (int nt = 0; nt < 4; nt++) mma_tf32(acc[mt][nt], af[mt], bf[nt]);
            }
        }
        // convert + store next chunk
        if (t + 1 < NCHUNKS) {
            uint32_t* As = sm + ((t + 1) & 1) * TILE_WORDS;
            uint32_t* Bs = sm + 2 * TILE_WORDS + ((t + 1) & 1) * TILE_WORDS;
#pragma unroll
            for (int j = 0; j < 2; j++) {
                int idx = tid + j * 256;
                int row = idx >> 2, c = idx & 3;
                uint4 ua = make_uint4(f2tf32(pa[j].x), f2tf32(pa[j].y), f2tf32(pa[j].z), f2tf32(pa[j].w));
                uint4 ub = make_uint4(f2tf32(pb[j].x), f2tf32(pb[j].y), f2tf32(pb[j].z), f2tf32(pb[j].w));
                *(uint4*)(As + row * LDS_STRIDE + c * 4) = ua;
                *(uint4*)(Bs + row * LDS_STRIDE + c * 4) = ub;
            }
        }
        __syncthreads();
    }

    // epilogue: write C + |v| partial
    float asum = 0.f;
#pragma unroll
    for (int mt = 0; mt < 4; mt++) {
        const int r0 = m0 + wm0 + mt * 16 + gid;
        const int r1 = r0 + 8;
#pragma unroll
        for (int nt = 0; nt < 4; nt++) {
            const int cc = n0 + wn0 + nt * 8 + tig * 2;
            float c0 = acc[mt][nt][0], c1 = acc[mt][nt][1];
            float c2 = acc[mt][nt][2], c3 = acc[mt][nt][3];
            *(float2*)(C + (size_t)r0 * DIMN + cc) = make_float2(c0, c1);
            *(float2*)(C + (size_t)r1 * DIMN + cc) = make_float2(c2, c3);
            asum += fabsf(c0) + fabsf(c1) + fabsf(c2) + fabsf(c3);
        }
    }
#pragma unroll
    for (int o = 16; o; o >>= 1) asum += __shfl_down_sync(0xffffffffu, asum, o);
    if (lane == 0) s_red[wid] = asum;
    __syncthreads();
    if (tid == 0) {
        float s = 0.f;
        for (int i = 0; i < 8; i++) s += s_red[i];
        g_pabs[blockIdx.y * gridDim.x + blockIdx.x] = s;
    }
}

// ============================ regulator ============================
__device__ __forceinline__ double blockReduce256d(double v, double* sh) {
#pragma unroll
    for (int o = 16; o; o >>= 1) v += __shfl_down_sync(0xffffffffu, v, o);
    if ((threadIdx.x & 31) == 0) sh[threadIdx.x >> 5] = v;
    __syncthreads();
    double r = 0.0;
    if (threadIdx.x == 0)
        for (int i = 0; i < 8; i++) r += sh[i];
    __syncthreads();
    return r;
}

__global__ __launch_bounds__(256) void k_regulator(const float* __restrict__ r1w,
                                                   const float* __restrict__ r1b,
                                                   const float* __restrict__ lng,
                                                   const float* __restrict__ lnb,
                                                   const float* __restrict__ r2w,
                                                   const float* __restrict__ r2b) {
    __shared__ double sh[8];
    const int tid = threadIdx.x;
    double a = 0, b = 0, c = 0, d = 0, e = 0;
    for (int i = tid; i < 1024; i += 256) { a += (double)g_px[i]; b += (double)g_pxx[i]; }
    for (int i = tid; i < 512; i += 256)  { c += (double)g_pw[i]; d += (double)g_pf[i]; }
    for (int i = tid; i < 2048; i += 256) { e += (double)g_pabs[i]; }
    a = blockReduce256d(a, sh);
    b = blockReduce256d(b, sh);
    c = blockReduce256d(c, sh);
    d = blockReduce256d(d, sh);
    e = blockReduce256d(e, sh);
    if (tid == 0) {
        const double cnt = (double)NR * (double)DIMN;
        double mean = a / cnt;
        float stress = (float)(b / cnt - mean * mean);
        float excit  = (float)(e / cnt);
        float fatig  = sqrtf((float)c);
        float sig[3] = {stress, excit, fatig};
        float h[16];
        float mu = 0.f;
#pragma unroll
        for (int i = 0; i < 16; i++) {
            h[i] = r1b[i] + sig[0] * r1w[i * 3 + 0] + sig[1] * r1w[i * 3 + 1] + sig[2] * r1w[i * 3 + 2];
            mu += h[i];
        }
        mu *= (1.0f / 16.0f);
        float var = 0.f;
#pragma unroll
        for (int i = 0; i < 16; i++) { float dd = h[i] - mu; var += dd * dd; }
        var *= (1.0f / 16.0f);
        float rstd = rsqrtf(var + LN_EPS);
#pragma unroll
        for (int i = 0; i < 16; i++) h[i] = tanhf((h[i] - mu) * rstd * lng[i] + lnb[i]);
#pragma unroll
        for (int i = 0; i < 3; i++) {
            float s = r2b[i];
#pragma unroll
            for (int j = 0; j < 16; j++) s += h[j] * r2w[i * 16 + j];
            g_ctrl[i] = sigmoidf_(s);
        }
        g_flag = (d > 0.0) ? 1 : 0;
    }
}

// ============================ flag-gated general fast-weight path ============================
__global__ __launch_bounds__(256, 2) void sgemm_nt_flag(const float* __restrict__ A,
                                                        const float* __restrict__ B,
                                                        float* __restrict__ C,
                                                        int M, int N, int K) {
    if (g_flag == 0) return;
    constexpr int BM = 128, BN = 128, BK = 8;
    __shared__ float As[2][BK][BM];
    __shared__ float Bs[2][BK][BN];
    const int tid = threadIdx.x;
    const int m0 = blockIdx.y * BM;
    const int n0 = blockIdx.x * BN;
    const int lr = tid >> 1;
    const int lc = (tid & 1) * 4;
    const int tx = tid & 15;
    const int ty = tid >> 4;
    const float* Aptr = A + (size_t)(m0 + lr) * K + lc;
    const float* Bptr = B + (size_t)(n0 + lr) * K + lc;
    float acc[8][8] = {};
    float4 pa = *(const float4*)Aptr;
    float4 pb = *(const float4*)Bptr;
    As[0][lc + 0][lr] = pa.x; As[0][lc + 1][lr] = pa.y; As[0][lc + 2][lr] = pa.z; As[0][lc + 3][lr] = pa.w;
    Bs[0][lc + 0][lr] = pb.x; Bs[0][lc + 1][lr] = pb.y; Bs[0][lc + 2][lr] = pb.z; Bs[0][lc + 3][lr] = pb.w;
    __syncthreads();
    const int T = K / BK;
    int buf = 0;
    for (int t = 0; t < T; ++t) {
        const bool has = (t + 1 < T);
        if (has) {
            pa = *(const float4*)(Aptr + (t + 1) * BK);
            pb = *(const float4*)(Bptr + (t + 1) * BK);
        }
#pragma unroll
        for (int k = 0; k < BK; ++k) {
            float4 a0 = *(const float4*)&As[buf][k][ty * 8];
            float4 a1 = *(const float4*)&As[buf][k][ty * 8 + 4];
            float4 b0 = *(const float4*)&Bs[buf][k][tx * 8];
            float4 b1 = *(const float4*)&Bs[buf][k][tx * 8 + 4];
            float av[8] = {a0.x, a0.y, a0.z, a0.w, a1.x, a1.y, a1.z, a1.w};
            float bv[8] = {b0.x, b0.y, b0.z, b0.w, b1.x, b1.y, b1.z, b1.w};
#pragma unroll
            for (int i = 0; i < 8; i++)
#pragma unroll
                for (int j = 0; j < 8; j++) acc[i][j] += av[i] * bv[j];
        }
        if (has) {
            int w = buf ^ 1;
            As[w][lc + 0][lr] = pa.x; As[w][lc + 1][lr] = pa.y; As[w][lc + 2][lr] = pa.z; As[w][lc + 3][lr] = pa.w;
            Bs[w][lc + 0][lr] = pb.x; Bs[w][lc + 1][lr] = pb.y; Bs[w][lc + 2][lr] = pb.z; Bs[w][lc + 3][lr] = pb.w;
            __syncthreads();
            buf = w;
        }
    }
#pragma unroll
    for (int i = 0; i < 8; i++) {
        size_t off = (size_t)(m0 + ty * 8 + i) * N + n0 + tx * 8;
        *(float4*)&C[off]     = make_float4(acc[i][0], acc[i][1], acc[i][2], acc[i][3]);
        *(float4*)&C[off + 4] = make_float4(acc[i][4], acc[i][5], acc[i][6], acc[i][7]);
    }
}

__global__ __launch_bounds__(256) void k_colsq() {
    if (g_flag == 0) return;
    const int j = blockIdx.x;
    float s = 0.f;
    for (int i = threadIdx.x; i < NR; i += blockDim.x) {
        float t = g_y[(size_t)i * DIMN + j];
        s += t * t;
    }
#pragma unroll
    for (int o = 16; o; o >>= 1) s += __shfl_down_sync(0xffffffffu, s, o);
    __shared__ float sh[8];
    if ((threadIdx.x & 31) == 0) sh[threadIdx.x >> 5] = s;
    __syncthreads();
    if (threadIdx.x == 0) {
        float t = 0.f;
        for (int i = 0; i < 8; i++) t += sh[i];
        g_colsq[j] = t;
    }
}

__global__ __launch_bounds__(256) void k_hebb(const float* __restrict__ Bx) {
    if (g_flag == 0) return;
    __shared__ float As[16][64];
    __shared__ float Bs[16][64];
    const int tid = threadIdx.x;
    const int m0 = blockIdx.y * 64, n0 = blockIdx.x * 64;
    const int lk = tid >> 4;
    const int lm = (tid & 15) * 4;
    const int tx = tid & 15, ty = tid >> 4;
    float acc[4][4] = {};
    for (int k0 = 0; k0 < NR; k0 += 16) {
        float4 a = *(const float4*)&g_y[(size_t)(k0 + lk) * DIMN + m0 + lm];
        float4 b = *(const float4*)&Bx[(size_t)(k0 + lk) * DIMN + n0 + lm];
        *(float4*)&As[lk][lm] = a;
        *(float4*)&Bs[lk][lm] = b;
        __syncthreads();
#pragma unroll
        for (int k = 0; k < 16; k++) {
            float av[4], bv[4];
#pragma unroll
            for (int i = 0; i < 4; i++) { av[i] = As[k][ty * 4 + i]; bv[i] = Bs[k][tx * 4 + i]; }
#pragma unroll
            for (int i = 0; i < 4; i++)
#pragma unroll
                for (int j = 0; j < 4; j++) acc[i][j] += av[i] * bv[j];
        }
        __syncthreads();
    }
    const float scale = 1.0f / (float)NR;
#pragma unroll
    for (int i = 0; i < 4; i++)
#pragma unroll
        for (int j = 0; j < 4; j++)
            g_hebb[(size_t)(m0 + ty * 4 + i) * DIMN + n0 + tx * 4 + j] = acc[i][j] * scale;
}

__global__ __launch_bounds__(256) void k_wfnew(const float* __restrict__ wf) {
    if (g_flag == 0) return;
    const float rate = g_ctrl[1] * 0.1f;
    const float invn = 1.0f / (float)NR;
    for (size_t idx = (size_t)blockIdx.x * blockDim.x + threadIdx.x;
         idx < (size_t)DIMN * DIMN; idx += (size_t)gridDim.x * blockDim.x) {
        int j = (int)(idx / DIMN);
        float w = wf[idx];
        float forget = g_colsq[j] * invn * w;
        g_wfnew[idx] = w + tanhf(g_hebb[idx] - forget) * rate;
    }
}

// ============================ fused gate + epilogue ============================
__global__ __launch_bounds__(256) void k_finalize(const float* __restrict__ gw,
                                                  const float* __restrict__ gb,
                                                  float* __restrict__ out) {
    __shared__ float row[DIMN];
    __shared__ float red[8];
    __shared__ float s_gate;
    const int r = blockIdx.x;
    const float4* vrow = (const float4*)(g_v + (size_t)r * DIMN);
    const float4* gw4 = (const float4*)gw;
    float p = 0.f;
    for (int i = threadIdx.x; i < DIMN / 4; i += 256) {
        float4 t = vrow[i];
        float4 g = gw4[i];
        ((float4*)row)[i] = t;
        p += t.x * g.x + t.y * g.y + t.z * g.z + t.w * g.w;
    }
#pragma unroll
    for (int o = 16; o; o >>= 1) p += __shfl_down_sync(0xffffffffu, p, o);
    if ((threadIdx.x & 31) == 0) red[threadIdx.x >> 5] = p;
    __syncthreads();
    if (threadIdx.x == 0) {
        float s = 0.f;
        for (int i = 0; i < 8; i++) s += red[i];
        s_gate = g_ctrl[0] * sigmoidf_(s + gb[0]);
    }
    __syncthreads();
    const float gate = s_gate;
    const int flag = g_flag;
    const float c2 = g_ctrl[2];
    float4* o4 = (float4*)(out + (size_t)r * DIMN);
    const float4* f4 = (const float4*)(g_fast + (size_t)r * DIMN);
    for (int i = threadIdx.x; i < DIMN / 4; i += 256) {
        float4 t = ((float4*)row)[i];
        if (flag) {
            float4 f = f4[i];
            t.x += f.x * c2; t.y += f.y * c2; t.z += f.z * c2; t.w += f.w * c2;
        }
        t.x *= gate; t.y *= gate; t.z *= gate; t.w *= gate;
        o4[i] = t;
    }
}

// ============================ launch ============================
extern "C" void kernel_launch(void* const* d_in, const int* in_sizes, int n_in,
                              void* d_out, int out_size) {
    const float* x     = (const float*)d_in[0];
    const float* Vw    = (const float*)d_in[1];
    const float* Wslow = (const float*)d_in[2];
    const float* gw    = (const float*)d_in[3];
    const float* gb    = (const float*)d_in[4];
    const float* r1w   = (const float*)d_in[5];
    const float* r1b   = (const float*)d_in[6];
    const float* lng   = (const float*)d_in[7];
    const float* lnb   = (const float*)d_in[8];
    const float* r2w   = (const float*)d_in[9];
    const float* r2b   = (const float*)d_in[10];
    const float* Wfast = (const float*)d_in[11];
    float* out = (float*)d_out;

    float *pv, *py, *pfast, *pwfnew;
    cudaGetSymbolAddress((void**)&pv, g_v);
    cudaGetSymbolAddress((void**)&py, g_y);
    cudaGetSymbolAddress((void**)&pfast, g_fast);
    cudaGetSymbolAddress((void**)&pwfnew, g_wfnew);

    cudaFuncSetAttribute(k_gemm_v, cudaFuncAttributeMaxDynamicSharedMemorySize, SMEM_GEMM_BYTES);

    k_stats_x<<<1024, 256>>>((const float4*)x, NR * DIMN / 4);
    k_stats_w<<<512, 256>>>((const float4*)Wslow, (const float4*)Wfast, DIMN * DIMN / 4);

    dim3 gg(DIMN / 128, NR / 128);   // (16, 128) -> 2048 CTAs
    k_gemm_v<<<gg, 256, SMEM_GEMM_BYTES>>>(x, Vw, pv);

    k_regulator<<<1, 256>>>(r1w, r1b, lng, lnb, r2w, r2b);

    // general fast-weight path; every kernel early-exits when W_fast == 0
    dim3 gv(DIMN / 128, NR / 128);
    sgemm_nt_flag<<<gv, 256>>>(x, Wfast, py, NR, DIMN, DIMN);
    k_colsq<<<DIMN, 256>>>();
    dim3 gh(DIMN / 64, DIMN / 64);
    k_hebb<<<gh, 256>>>(x);
    k_wfnew<<<4096, 256>>>(Wfast);
    sgemm_nt_flag<<<gv, 256>>>(x, pwfnew, pfast, NR, DIMN, DIMN);

    k_finalize<<<NR, 256>>>(gw, gb, out);
}

// round 8
// speedup vs baseline: 3.0705x; 1.1875x over previous
#include <cuda_runtime.h>
#include <cuda_bf16.h>
#include <math.h>
#include <stdint.h>

#define DIMN 2048
#define NR   16384
#define LN_EPS 1e-5f

// ============================ scratch (device globals) ============================
__device__ float g_v[(size_t)NR * DIMN];
__device__ float g_y[(size_t)NR * DIMN];
__device__ float g_fast[(size_t)NR * DIMN];
__device__ float g_hebb[(size_t)DIMN * DIMN];
__device__ float g_wfnew[(size_t)DIMN * DIMN];
__device__ float g_colsq[DIMN];
__device__ float g_px[1024];
__device__ float g_pxx[1024];
__device__ float g_pw[512];
__device__ int   g_pf[512];
__device__ float g_pabs[2048];   // one partial per GEMM CTA (16 x 128 grid)
__device__ float g_ctrl[3];
__device__ int   g_flag;

__device__ __forceinline__ float sigmoidf_(float x) { return 1.0f / (1.0f + expf(-x)); }

__device__ __forceinline__ uint32_t smem_u32(const void* p) {
    uint32_t a;
    asm("{ .reg .u64 t; cvta.to.shared.u64 t, %1; cvt.u32.u64 %0, t; }" : "=r"(a) : "l"(p));
    return a;
}

__device__ __forceinline__ uint32_t f2tf32(float f) {
    uint32_t r;
    asm("cvt.rna.tf32.f32 %0, %1;" : "=r"(r) : "f"(f));
    return r;
}

__device__ __forceinline__ void mma_tf32(float c[4], const uint32_t a[4], const uint32_t b[2]) {
    asm volatile(
        "mma.sync.aligned.m16n8k8.row.col.f32.tf32.tf32.f32 "
        "{%0,%1,%2,%3}, {%4,%5,%6,%7}, {%8,%9}, {%0,%1,%2,%3};"
        : "+f"(c[0]), "+f"(c[1]), "+f"(c[2]), "+f"(c[3])
        : "r"(a[0]), "r"(a[1]), "r"(a[2]), "r"(a[3]), "r"(b[0]), "r"(b[1]));
}

__device__ __forceinline__ void ldsm_x4(uint32_t& r0, uint32_t& r1, uint32_t& r2, uint32_t& r3,
                                        uint32_t smem_addr) {
    asm volatile("ldmatrix.sync.aligned.m8n8.x4.shared.b16 {%0,%1,%2,%3}, [%4];"
                 : "=r"(r0), "=r"(r1), "=r"(r2), "=r"(r3) : "r"(smem_addr));
}

// ============================ stats ============================
__global__ __launch_bounds__(256) void k_stats_x(const float4* __restrict__ x, int n4) {
    float s = 0.f, s2 = 0.f;
    for (int i = blockIdx.x * blockDim.x + threadIdx.x; i < n4; i += gridDim.x * blockDim.x) {
        float4 t = x[i];
        s  += t.x + t.y + t.z + t.w;
        s2 += t.x * t.x + t.y * t.y + t.z * t.z + t.w * t.w;
    }
#pragma unroll
    for (int o = 16; o; o >>= 1) {
        s  += __shfl_down_sync(0xffffffffu, s, o);
        s2 += __shfl_down_sync(0xffffffffu, s2, o);
    }
    __shared__ float sh1[8], sh2[8];
    if ((threadIdx.x & 31) == 0) { sh1[threadIdx.x >> 5] = s; sh2[threadIdx.x >> 5] = s2; }
    __syncthreads();
    if (threadIdx.x == 0) {
        float a = 0.f, b = 0.f;
        for (int i = 0; i < 8; i++) { a += sh1[i]; b += sh2[i]; }
        g_px[blockIdx.x] = a;
        g_pxx[blockIdx.x] = b;
    }
}

__global__ __launch_bounds__(256) void k_stats_w(const float4* __restrict__ ws,
                                                 const float4* __restrict__ wf, int n4) {
    float s2 = 0.f;
    int cnt = 0;
    for (int i = blockIdx.x * blockDim.x + threadIdx.x; i < n4; i += gridDim.x * blockDim.x) {
        float4 a = ws[i];
        s2 += a.x * a.x + a.y * a.y + a.z * a.z + a.w * a.w;
        float4 b = wf[i];
        cnt += (b.x != 0.f) + (b.y != 0.f) + (b.z != 0.f) + (b.w != 0.f);
    }
#pragma unroll
    for (int o = 16; o; o >>= 1) {
        s2  += __shfl_down_sync(0xffffffffu, s2, o);
        cnt += __shfl_down_sync(0xffffffffu, cnt, o);
    }
    __shared__ float sh1[8];
    __shared__ int   sh2[8];
    if ((threadIdx.x & 31) == 0) { sh1[threadIdx.x >> 5] = s2; sh2[threadIdx.x >> 5] = cnt; }
    __syncthreads();
    if (threadIdx.x == 0) {
        float a = 0.f; int b = 0;
        for (int i = 0; i < 8; i++) { a += sh1[i]; b += sh2[i]; }
        g_pw[blockIdx.x] = a;
        g_pf[blockIdx.x] = b;
    }
}

// ============================ tf32 mma.sync GEMM: v = x @ V^T ============================
// C[M,N] = A[M,K] @ B[N,K]^T, K-major. CTA tile 128x128, 256 threads (8 warps),
// warp tile 64x32, K-chunk 16, 2 CTAs/SM (40KB smem, <=128 regs).
// Fragments loaded via ldmatrix.x4 (bank-conflict-free with 20-word row stride);
// cvt.rna.tf32 at STS time.
#define GKC 16
#define NCHUNKS (DIMN / GKC)            // 128
#define LDS_STRIDE 20
#define TILE_WORDS (128 * LDS_STRIDE)   // 2560
#define SMEM_GEMM_BYTES (4 * TILE_WORDS * 4)  // A0,A1,B0,B1 = 40960

__global__ void __launch_bounds__(256, 2) k_gemm_v(const float* __restrict__ A,
                                                   const float* __restrict__ B,
                                                   float* __restrict__ C) {
    extern __shared__ uint32_t sm[];
    __shared__ float s_red[8];
    const uint32_t sbase = smem_u32(sm);
    const int tid = threadIdx.x;
    const int wid = tid >> 5;
    const int lane = tid & 31;
    const int gid = lane >> 2;        // 0..7
    const int tig = lane & 3;         // 0..3
    const int m0 = blockIdx.y * 128;
    const int n0 = blockIdx.x * 128;
    const int wm0 = (wid & 1) * 64;   // warp row offset in tile
    const int wn0 = (wid >> 1) * 32;  // warp col offset in tile

    // ldmatrix per-lane offsets (in words):
    //   A x4 (one mt): m0=(r0-7,k0-3) m1=(r8-15,k0-3) m2=(r0-7,k4-7) m3=(r8-15,k4-7)
    //     lane row = lane&15, col group = (lane>>4)*4
    //   B x4 (nt pair): m0=(n0-7,k0-3) m1=(n0-7,k4-7) m2=(n8-15,k0-3) m3=(n8-15,k4-7)
    //     lane row = (lane&7)+(lane>>4)*8, col group = ((lane>>3)&1)*4
    const uint32_t a_lane_off = (uint32_t)((lane & 15) * LDS_STRIDE + (lane >> 4) * 4) * 4;
    const uint32_t b_lane_off = (uint32_t)(((lane & 7) + (lane >> 4) * 8) * LDS_STRIDE
                                           + ((lane >> 3) & 1) * 4) * 4;

    // staged loads: each operand tile is 128 rows x 16 cols = 512 float4; 2/thread.
    float4 pa[2], pb[2];
#pragma unroll
    for (int j = 0; j < 2; j++) {
        int idx = tid + j * 256;
        int row = idx >> 2, c = idx & 3;
        pa[j] = *(const float4*)(A + (size_t)(m0 + row) * DIMN + c * 4);
        pb[j] = *(const float4*)(B + (size_t)(n0 + row) * DIMN + c * 4);
    }
    // convert + store chunk 0 into buffer 0
    {
        uint32_t* As = sm;
        uint32_t* Bs = sm + 2 * TILE_WORDS;
#pragma unroll
        for (int j = 0; j < 2; j++) {
            int idx = tid + j * 256;
            int row = idx >> 2, c = idx & 3;
            uint4 ua = make_uint4(f2tf32(pa[j].x), f2tf32(pa[j].y), f2tf32(pa[j].z), f2tf32(pa[j].w));
            uint4 ub = make_uint4(f2tf32(pb[j].x), f2tf32(pb[j].y), f2tf32(pb[j].z), f2tf32(pb[j].w));
            *(uint4*)(As + row * LDS_STRIDE + c * 4) = ua;
            *(uint4*)(Bs + row * LDS_STRIDE + c * 4) = ub;
        }
    }
    __syncthreads();

    float acc[4][4][4];
#pragma unroll
    for (int mt = 0; mt < 4; mt++)
#pragma unroll
        for (int nt = 0; nt < 4; nt++)
#pragma unroll
            for (int r = 0; r < 4; r++) acc[mt][nt][r] = 0.f;

#pragma unroll 1
    for (int t = 0; t < NCHUNKS; ++t) {
        // prefetch next chunk to regs
        if (t + 1 < NCHUNKS) {
            const int k0 = (t + 1) * GKC;
#pragma unroll
            for (int j = 0; j < 2; j++) {
                int idx = tid + j * 256;
                int row = idx >> 2, c = idx & 3;
                pa[j] = *(const float4*)(A + (size_t)(m0 + row) * DIMN + k0 + c * 4);
                pb[j] = *(const float4*)(B + (size_t)(n0 + row) * DIMN + k0 + c * 4);
            }
        }
        // compute chunk t (fragments via ldmatrix.x4)
        {
            const uint32_t abase = sbase + ((t & 1) * TILE_WORDS) * 4;
            const uint32_t bbase = sbase + ((2 + (t & 1)) * TILE_WORDS) * 4;
#pragma unroll
            for (int s = 0; s < 2; s++) {
                const int kb = s * 8;
                uint32_t af[4][4];
#pragma unroll
                for (int mt = 0; mt < 4; mt++) {
                    const uint32_t addr = abase
                        + (uint32_t)(((wm0 + mt * 16) * LDS_STRIDE + kb) * 4) + a_lane_off;
                    ldsm_x4(af[mt][0], af[mt][1], af[mt][2], af[mt][3], addr);
                }
                uint32_t bf[4][2];
#pragma unroll
                for (int np = 0; np < 2; np++) {
                    const uint32_t addr = bbase
                        + (uint32_t)(((wn0 + np * 16) * LDS_STRIDE + kb) * 4) + b_lane_off;
                    ldsm_x4(bf[2 * np][0], bf[2 * np][1], bf[2 * np + 1][0], bf[2 * np + 1][1], addr);
                }
#pragma unroll
                for (int mt = 0; mt < 4; mt++)
#pragma unroll
                    for (int nt = 0; nt < 4; nt++) mma_tf32(acc[mt][nt], af[mt], bf[nt]);
            }
        }
        // convert + store next chunk
        if (t + 1 < NCHUNKS) {
            uint32_t* As = sm + ((t + 1) & 1) * TILE_WORDS;
            uint32_t* Bs = sm + (2 + ((t + 1) & 1)) * TILE_WORDS;
#pragma unroll
            for (int j = 0; j < 2; j++) {
                int idx = tid + j * 256;
                int row = idx >> 2, c = idx & 3;
                uint4 ua = make_uint4(f2tf32(pa[j].x), f2tf32(pa[j].y), f2tf32(pa[j].z), f2tf32(pa[j].w));
                uint4 ub = make_uint4(f2tf32(pb[j].x), f2tf32(pb[j].y), f2tf32(pb[j].z), f2tf32(pb[j].w));
                *(uint4*)(As + row * LDS_STRIDE + c * 4) = ua;
                *(uint4*)(Bs + row * LDS_STRIDE + c * 4) = ub;
            }
        }
        __syncthreads();
    }

    // epilogue: write C + |v| partial
    float asum = 0.f;
#pragma unroll
    for (int mt = 0; mt < 4; mt++) {
        const int r0 = m0 + wm0 + mt * 16 + gid;
        const int r1 = r0 + 8;
#pragma unroll
        for (int nt = 0; nt < 4; nt++) {
            const int cc = n0 + wn0 + nt * 8 + tig * 2;
            float c0 = acc[mt][nt][0], c1 = acc[mt][nt][1];
            float c2 = acc[mt][nt][2], c3 = acc[mt][nt][3];
            *(float2*)(C + (size_t)r0 * DIMN + cc) = make_float2(c0, c1);
            *(float2*)(C + (size_t)r1 * DIMN + cc) = make_float2(c2, c3);
            asum += fabsf(c0) + fabsf(c1) + fabsf(c2) + fabsf(c3);
        }
    }
#pragma unroll
    for (int o = 16; o; o >>= 1) asum += __shfl_down_sync(0xffffffffu, asum, o);
    if (lane == 0) s_red[wid] = asum;
    __syncthreads();
    if (tid == 0) {
        float s = 0.f;
        for (int i = 0; i < 8; i++) s += s_red[i];
        g_pabs[blockIdx.y * gridDim.x + blockIdx.x] = s;
    }
}

// ============================ regulator ============================
__device__ __forceinline__ double blockReduce256d(double v, double* sh) {
#pragma unroll
    for (int o = 16; o; o >>= 1) v += __shfl_down_sync(0xffffffffu, v, o);
    if ((threadIdx.x & 31) == 0) sh[threadIdx.x >> 5] = v;
    __syncthreads();
    double r = 0.0;
    if (threadIdx.x == 0)
        for (int i = 0; i < 8; i++) r += sh[i];
    __syncthreads();
    return r;
}

__global__ __launch_bounds__(256) void k_regulator(const float* __restrict__ r1w,
                                                   const float* __restrict__ r1b,
                                                   const float* __restrict__ lng,
                                                   const float* __restrict__ lnb,
                                                   const float* __restrict__ r2w,
                                                   const float* __restrict__ r2b) {
    __shared__ double sh[8];
    const int tid = threadIdx.x;
    double a = 0, b = 0, c = 0, d = 0, e = 0;
    for (int i = tid; i < 1024; i += 256) { a += (double)g_px[i]; b += (double)g_pxx[i]; }
    for (int i = tid; i < 512; i += 256)  { c += (double)g_pw[i]; d += (double)g_pf[i]; }
    for (int i = tid; i < 2048; i += 256) { e += (double)g_pabs[i]; }
    a = blockReduce256d(a, sh);
    b = blockReduce256d(b, sh);
    c = blockReduce256d(c, sh);
    d = blockReduce256d(d, sh);
    e = blockReduce256d(e, sh);
    if (tid == 0) {
        const double cnt = (double)NR * (double)DIMN;
        double mean = a / cnt;
        float stress = (float)(b / cnt - mean * mean);
        float excit  = (float)(e / cnt);
        float fatig  = sqrtf((float)c);
        float sig[3] = {stress, excit, fatig};
        float h[16];
        float mu = 0.f;
#pragma unroll
        for (int i = 0; i < 16; i++) {
            h[i] = r1b[i] + sig[0] * r1w[i * 3 + 0] + sig[1] * r1w[i * 3 + 1] + sig[2] * r1w[i * 3 + 2];
            mu += h[i];
        }
        mu *= (1.0f / 16.0f);
        float var = 0.f;
#pragma unroll
        for (int i = 0; i < 16; i++) { float dd = h[i] - mu; var += dd * dd; }
        var *= (1.0f / 16.0f);
        float rstd = rsqrtf(var + LN_EPS);
#pragma unroll
        for (int i = 0; i < 16; i++) h[i] = tanhf((h[i] - mu) * rstd * lng[i] + lnb[i]);
#pragma unroll
        for (int i = 0; i < 3; i++) {
            float s = r2b[i];
#pragma unroll
            for (int j = 0; j < 16; j++) s += h[j] * r2w[i * 16 + j];
            g_ctrl[i] = sigmoidf_(s);
        }
        g_flag = (d > 0.0) ? 1 : 0;
    }
}

// ============================ flag-gated general fast-weight path ============================
__global__ __launch_bounds__(256, 2) void sgemm_nt_flag(const float* __restrict__ A,
                                                        const float* __restrict__ B,
                                                        float* __restrict__ C,
                                                        int M, int N, int K) {
    if (g_flag == 0) return;
    constexpr int BM = 128, BN = 128, BK = 8;
    __shared__ float As[2][BK][BM];
    __shared__ float Bs[2][BK][BN];
    const int tid = threadIdx.x;
    const int m0 = blockIdx.y * BM;
    const int n0 = blockIdx.x * BN;
    const int lr = tid >> 1;
    const int lc = (tid & 1) * 4;
    const int tx = tid & 15;
    const int ty = tid >> 4;
    const float* Aptr = A + (size_t)(m0 + lr) * K + lc;
    const float* Bptr = B + (size_t)(n0 + lr) * K + lc;
    float acc[8][8] = {};
    float4 pa = *(const float4*)Aptr;
    float4 pb = *(const float4*)Bptr;
    As[0][lc + 0][lr] = pa.x; As[0][lc + 1][lr] = pa.y; As[0][lc + 2][lr] = pa.z; As[0][lc + 3][lr] = pa.w;
    Bs[0][lc + 0][lr] = pb.x; Bs[0][lc + 1][lr] = pb.y; Bs[0][lc + 2][lr] = pb.z; Bs[0][lc + 3][lr] = pb.w;
    __syncthreads();
    const int T = K / BK;
    int buf = 0;
    for (int t = 0; t < T; ++t) {
        const bool has = (t + 1 < T);
        if (has) {
            pa = *(const float4*)(Aptr + (t + 1) * BK);
            pb = *(const float4*)(Bptr + (t + 1) * BK);
        }
#pragma unroll
        for (int k = 0; k < BK; ++k) {
            float4 a0 = *(const float4*)&As[buf][k][ty * 8];
            float4 a1 = *(const float4*)&As[buf][k][ty * 8 + 4];
            float4 b0 = *(const float4*)&Bs[buf][k][tx * 8];
            float4 b1 = *(const float4*)&Bs[buf][k][tx * 8 + 4];
            float av[8] = {a0.x, a0.y, a0.z, a0.w, a1.x, a1.y, a1.z, a1.w};
            float bv[8] = {b0.x, b0.y, b0.z, b0.w, b1.x, b1.y, b1.z, b1.w};
#pragma unroll
            for (int i = 0; i < 8; i++)
#pragma unroll
                for (int j = 0; j < 8; j++) acc[i][j] += av[i] * bv[j];
        }
        if (has) {
            int w = buf ^ 1;
            As[w][lc + 0][lr] = pa.x; As[w][lc + 1][lr] = pa.y; As[w][lc + 2][lr] = pa.z; As[w][lc + 3][lr] = pa.w;
            Bs[w][lc + 0][lr] = pb.x; Bs[w][lc + 1][lr] = pb.y; Bs[w][lc + 2][lr] = pb.z; Bs[w][lc + 3][lr] = pb.w;
            __syncthreads();
            buf = w;
        }
    }
#pragma unroll
    for (int i = 0; i < 8; i++) {
        size_t off = (size_t)(m0 + ty * 8 + i) * N + n0 + tx * 8;
        *(float4*)&C[off]     = make_float4(acc[i][0], acc[i][1], acc[i][2], acc[i][3]);
        *(float4*)&C[off + 4] = make_float4(acc[i][4], acc[i][5], acc[i][6], acc[i][7]);
    }
}

__global__ __launch_bounds__(256) void k_colsq() {
    if (g_flag == 0) return;
    const int j = blockIdx.x;
    float s = 0.f;
    for (int i = threadIdx.x; i < NR; i += blockDim.x) {
        float t = g_y[(size_t)i * DIMN + j];
        s += t * t;
    }
#pragma unroll
    for (int o = 16; o; o >>= 1) s += __shfl_down_sync(0xffffffffu, s, o);
    __shared__ float sh[8];
    if ((threadIdx.x & 31) == 0) sh[threadIdx.x >> 5] = s;
    __syncthreads();
    if (threadIdx.x == 0) {
        float t = 0.f;
        for (int i = 0; i < 8; i++) t += sh[i];
        g_colsq[j] = t;
    }
}

__global__ __launch_bounds__(256) void k_hebb(const float* __restrict__ Bx) {
    if (g_flag == 0) return;
    __shared__ float As[16][64];
    __shared__ float Bs[16][64];
    const int tid = threadIdx.x;
    const int m0 = blockIdx.y * 64, n0 = blockIdx.x * 64;
    const int lk = tid >> 4;
    const int lm = (tid & 15) * 4;
    const int tx = tid & 15, ty = tid >> 4;
    float acc[4][4] = {};
    for (int k0 = 0; k0 < NR; k0 += 16) {
        float4 a = *(const float4*)&g_y[(size_t)(k0 + lk) * DIMN + m0 + lm];
        float4 b = *(const float4*)&Bx[(size_t)(k0 + lk) * DIMN + n0 + lm];
        *(float4*)&As[lk][lm] = a;
        *(float4*)&Bs[lk][lm] = b;
        __syncthreads();
#pragma unroll
        for (int k = 0; k < 16; k++) {
            float av[4], bv[4];
#pragma unroll
            for (int i = 0; i < 4; i++) { av[i] = As[k][ty * 4 + i]; bv[i] = Bs[k][tx * 4 + i]; }
#pragma unroll
            for (int i = 0; i < 4; i++)
#pragma unroll
                for (int j = 0; j < 4; j++) acc[i][j] += av[i] * bv[j];
        }
        __syncthreads();
    }
    const float scale = 1.0f / (float)NR;
#pragma unroll
    for (int i = 0; i < 4; i++)
#pragma unroll
        for (int j = 0; j < 4; j++)
            g_hebb[(size_t)(m0 + ty * 4 + i) * DIMN + n0 + tx * 4 + j] = acc[i][j] * scale;
}

__global__ __launch_bounds__(256) void k_wfnew(const float* __restrict__ wf) {
    if (g_flag == 0) return;
    const float rate = g_ctrl[1] * 0.1f;
    const float invn = 1.0f / (float)NR;
    for (size_t idx = (size_t)blockIdx.x * blockDim.x + threadIdx.x;
         idx < (size_t)DIMN * DIMN; idx += (size_t)gridDim.x * blockDim.x) {
        int j = (int)(idx / DIMN);
        float w = wf[idx];
        float forget = g_colsq[j] * invn * w;
        g_wfnew[idx] = w + tanhf(g_hebb[idx] - forget) * rate;
    }
}

// ============================ fused gate + epilogue ============================
__global__ __launch_bounds__(256) void k_finalize(const float* __restrict__ gw,
                                                  const float* __restrict__ gb,
                                                  float* __restrict__ out) {
    __shared__ float row[DIMN];
    __shared__ float red[8];
    __shared__ float s_gate;
    const int r = blockIdx.x;
    const float4* vrow = (const float4*)(g_v + (size_t)r * DIMN);
    const float4* gw4 = (const float4*)gw;
    float p = 0.f;
    for (int i = threadIdx.x; i < DIMN / 4; i += 256) {
        float4 t = vrow[i];
        float4 g = gw4[i];
        ((float4*)row)[i] = t;
        p += t.x * g.x + t.y * g.y + t.z * g.z + t.w * g.w;
    }
#pragma unroll
    for (int o = 16; o; o >>= 1) p += __shfl_down_sync(0xffffffffu, p, o);
    if ((threadIdx.x & 31) == 0) red[threadIdx.x >> 5] = p;
    __syncthreads();
    if (threadIdx.x == 0) {
        float s = 0.f;
        for (int i = 0; i < 8; i++) s += red[i];
        s_gate = g_ctrl[0] * sigmoidf_(s + gb[0]);
    }
    __syncthreads();
    const float gate = s_gate;
    const int flag = g_flag;
    const float c2 = g_ctrl[2];
    float4* o4 = (float4*)(out + (size_t)r * DIMN);
    const float4* f4 = (const float4*)(g_fast + (size_t)r * DIMN);
    for (int i = threadIdx.x; i < DIMN / 4; i += 256) {
        float4 t = ((float4*)row)[i];
        if (flag) {
            float4 f = f4[i];
            t.x += f.x * c2; t.y += f.y * c2; t.z += f.z * c2; t.w += f.w * c2;
        }
        t.x *= gate; t.y *= gate; t.z *= gate; t.w *= gate;
        o4[i] = t;
    }
}

// ============================ launch ============================
extern "C" void kernel_launch(void* const* d_in, const int* in_sizes, int n_in,
                              void* d_out, int out_size) {
    const float* x     = (const float*)d_in[0];
    const float* Vw    = (const float*)d_in[1];
    const float* Wslow = (const float*)d_in[2];
    const float* gw    = (const float*)d_in[3];
    const float* gb    = (const float*)d_in[4];
    const float* r1w   = (const float*)d_in[5];
    const float* r1b   = (const float*)d_in[6];
    const float* lng   = (const float*)d_in[7];
    const float* lnb   = (const float*)d_in[8];
    const float* r2w   = (const float*)d_in[9];
    const float* r2b   = (const float*)d_in[10];
    const float* Wfast = (const float*)d_in[11];
    float* out = (float*)d_out;

    float *pv, *py, *pfast, *pwfnew;
    cudaGetSymbolAddress((void**)&pv, g_v);
    cudaGetSymbolAddress((void**)&py, g_y);
    cudaGetSymbolAddress((void**)&pfast, g_fast);
    cudaGetSymbolAddress((void**)&pwfnew, g_wfnew);

    cudaFuncSetAttribute(k_gemm_v, cudaFuncAttributeMaxDynamicSharedMemorySize, SMEM_GEMM_BYTES);

    k_stats_x<<<1024, 256>>>((const float4*)x, NR * DIMN / 4);
    k_stats_w<<<512, 256>>>((const float4*)Wslow, (const float4*)Wfast, DIMN * DIMN / 4);

    dim3 gg(DIMN / 128, NR / 128);   // (16, 128) -> 2048 CTAs
    k_gemm_v<<<gg, 256, SMEM_GEMM_BYTES>>>(x, Vw, pv);

    k_regulator<<<1, 256>>>(r1w, r1b, lng, lnb, r2w, r2b);

    // general fast-weight path; every kernel early-exits when W_fast == 0
    dim3 gv(DIMN / 128, NR / 128);
    sgemm_nt_flag<<<gv, 256>>>(x, Wfast, py, NR, DIMN, DIMN);
    k_colsq<<<DIMN, 256>>>();
    dim3 gh(DIMN / 64, DIMN / 64);
    k_hebb<<<gh, 256>>>(x);
    k_wfnew<<<4096, 256>>>(Wfast);
    sgemm_nt_flag<<<gv, 256>>>(x, pwfnew, pfast, NR, DIMN, DIMN);

    k_finalize<<<NR, 256>>>(gw, gb, out);
}

// round 12
// speedup vs baseline: 3.5752x; 1.1644x over previous
#include <cuda_runtime.h>
#include <cuda_bf16.h>
#include <math.h>
#include <stdint.h>

#define DIMN 2048
#define NR   16384
#define LN_EPS 1e-5f

// ============================ scratch (device globals) ============================
__device__ float g_v[(size_t)NR * DIMN];
__device__ float g_y[(size_t)NR * DIMN];
__device__ float g_fast[(size_t)NR * DIMN];
__device__ float g_hebb[(size_t)DIMN * DIMN];
__device__ float g_wfnew[(size_t)DIMN * DIMN];
__device__ float g_colsq[DIMN];
__device__ float g_px[1024];
__device__ float g_pxx[1024];
__device__ float g_pw[512];
__device__ int   g_pf[512];
__device__ float g_pabs[2048];   // one partial per GEMM CTA (16 x 128 grid)
__device__ float g_ctrl[3];
__device__ int   g_flag;

__device__ __forceinline__ float sigmoidf_(float x) { return 1.0f / (1.0f + expf(-x)); }

__device__ __forceinline__ uint32_t smem_u32(const void* p) {
    uint32_t a;
    asm("{ .reg .u64 t; cvta.to.shared.u64 t, %1; cvt.u32.u64 %0, t; }" : "=r"(a) : "l"(p));
    return a;
}

__device__ __forceinline__ uint32_t f2tf32(float f) {
    uint32_t r;
    asm("cvt.rna.tf32.f32 %0, %1;" : "=r"(r) : "f"(f));
    return r;
}

__device__ __forceinline__ void mma_tf32(float c[4], const uint32_t a[4], const uint32_t b[2]) {
    asm volatile(
        "mma.sync.aligned.m16n8k8.row.col.f32.tf32.tf32.f32 "
        "{%0,%1,%2,%3}, {%4,%5,%6,%7}, {%8,%9}, {%0,%1,%2,%3};"
        : "+f"(c[0]), "+f"(c[1]), "+f"(c[2]), "+f"(c[3])
        : "r"(a[0]), "r"(a[1]), "r"(a[2]), "r"(a[3]), "r"(b[0]), "r"(b[1]));
}

__device__ __forceinline__ void ldsm_x4(uint32_t& r0, uint32_t& r1, uint32_t& r2, uint32_t& r3,
                                        uint32_t smem_addr) {
    asm volatile("ldmatrix.sync.aligned.m8n8.x4.shared.b16 {%0,%1,%2,%3}, [%4];"
                 : "=r"(r0), "=r"(r1), "=r"(r2), "=r"(r3) : "r"(smem_addr));
}

// ============================ stats ============================
__global__ __launch_bounds__(256) void k_stats_x(const float4* __restrict__ x, int n4) {
    float s = 0.f, s2 = 0.f;
    for (int i = blockIdx.x * blockDim.x + threadIdx.x; i < n4; i += gridDim.x * blockDim.x) {
        float4 t = x[i];
        s  += t.x + t.y + t.z + t.w;
        s2 += t.x * t.x + t.y * t.y + t.z * t.z + t.w * t.w;
    }
#pragma unroll
    for (int o = 16; o; o >>= 1) {
        s  += __shfl_down_sync(0xffffffffu, s, o);
        s2 += __shfl_down_sync(0xffffffffu, s2, o);
    }
    __shared__ float sh1[8], sh2[8];
    if ((threadIdx.x & 31) == 0) { sh1[threadIdx.x >> 5] = s; sh2[threadIdx.x >> 5] = s2; }
    __syncthreads();
    if (threadIdx.x == 0) {
        float a = 0.f, b = 0.f;
        for (int i = 0; i < 8; i++) { a += sh1[i]; b += sh2[i]; }
        g_px[blockIdx.x] = a;
        g_pxx[blockIdx.x] = b;
    }
}

__global__ __launch_bounds__(256) void k_stats_w(const float4* __restrict__ ws,
                                                 const float4* __restrict__ wf, int n4) {
    float s2 = 0.f;
    int cnt = 0;
    for (int i = blockIdx.x * blockDim.x + threadIdx.x; i < n4; i += gridDim.x * blockDim.x) {
        float4 a = ws[i];
        s2 += a.x * a.x + a.y * a.y + a.z * a.z + a.w * a.w;
        float4 b = wf[i];
        cnt += (b.x != 0.f) + (b.y != 0.f) + (b.z != 0.f) + (b.w != 0.f);
    }
#pragma unroll
    for (int o = 16; o; o >>= 1) {
        s2  += __shfl_down_sync(0xffffffffu, s2, o);
        cnt += __shfl_down_sync(0xffffffffu, cnt, o);
    }
    __shared__ float sh1[8];
    __shared__ int   sh2[8];
    if ((threadIdx.x & 31) == 0) { sh1[threadIdx.x >> 5] = s2; sh2[threadIdx.x >> 5] = cnt; }
    __syncthreads();
    if (threadIdx.x == 0) {
        float a = 0.f; int b = 0;
        for (int i = 0; i < 8; i++) { a += sh1[i]; b += sh2[i]; }
        g_pw[blockIdx.x] = a;
        g_pf[blockIdx.x] = b;
    }
}

// ============================ tf32 mma.sync GEMM: v = x @ V^T ============================
// C[M,N] = A[M,K] @ B[N,K]^T, K-major. CTA tile 128x128, 256 threads (8 warps),
// warp tile 64x32, K-chunk 32, 2 CTAs/SM (73.7KB smem, <=128 regs via 2-phase staging).
// Fragments via ldmatrix.x4 (conflict-free at 36-word row stride); cvt.rna at STS time.
#define GKC 32
#define NCHUNKS (DIMN / GKC)            // 64
#define LDS_STRIDE 36
#define TILE_WORDS (128 * LDS_STRIDE)   // 4608
#define SMEM_GEMM_BYTES (4 * TILE_WORDS * 4)  // A0,A1,B0,B1 = 73728

__global__ void __launch_bounds__(256, 2) k_gemm_v(const float* __restrict__ A,
                                                   const float* __restrict__ B,
                                                   float* __restrict__ C) {
    extern __shared__ uint32_t sm[];
    __shared__ float s_red[8];
    const uint32_t sbase = smem_u32(sm);
    const int tid = threadIdx.x;
    const int wid = tid >> 5;
    const int lane = tid & 31;
    const int gid = lane >> 2;        // 0..7
    const int tig = lane & 3;         // 0..3
    const int m0 = blockIdx.y * 128;
    const int n0 = blockIdx.x * 128;
    const int wm0 = (wid & 1) * 64;   // warp row offset in tile
    const int wn0 = (wid >> 1) * 32;  // warp col offset in tile

    // ldmatrix per-lane offsets (words*4 = bytes):
    const uint32_t a_lane_off = (uint32_t)((lane & 15) * LDS_STRIDE + (lane >> 4) * 4) * 4;
    const uint32_t b_lane_off = (uint32_t)(((lane & 7) + (lane >> 4) * 8) * LDS_STRIDE
                                           + ((lane >> 3) & 1) * 4) * 4;

    // global-load mapping: operand tile = 128 rows x 32 floats = 1024 float4, 4/thread.
    // idx = tid + j*256; row = idx>>3 (8 float4 per row), c = idx&7.
    // phase 1 stages j=0,1; phase 2 stages j=2,3.

    // ---- prologue: load chunk 0 fully into buffer 0 ----
    {
        uint32_t* As = sm;
        uint32_t* Bs = sm + 2 * TILE_WORDS;
#pragma unroll
        for (int j = 0; j < 4; j++) {
            int idx = tid + j * 256;
            int row = idx >> 3, c = idx & 7;
            float4 va = *(const float4*)(A + (size_t)(m0 + row) * DIMN + c * 4);
            float4 vb = *(const float4*)(B + (size_t)(n0 + row) * DIMN + c * 4);
            uint4 ua = make_uint4(f2tf32(va.x), f2tf32(va.y), f2tf32(va.z), f2tf32(va.w));
            uint4 ub = make_uint4(f2tf32(vb.x), f2tf32(vb.y), f2tf32(vb.z), f2tf32(vb.w));
            *(uint4*)(As + row * LDS_STRIDE + c * 4) = ua;
            *(uint4*)(Bs + row * LDS_STRIDE + c * 4) = ub;
        }
    }
    __syncthreads();

    float acc[4][4][4];
#pragma unroll
    for (int mt = 0; mt < 4; mt++)
#pragma unroll
        for (int nt = 0; nt < 4; nt++)
#pragma unroll
            for (int r = 0; r < 4; r++) acc[mt][nt][r] = 0.f;

    float4 pa[2], pb[2];

#pragma unroll 1
    for (int t = 0; t < NCHUNKS; ++t) {
        const int buf = t & 1;
        const int nbuf = buf ^ 1;
        const uint32_t abase = sbase + (buf * TILE_WORDS) * 4;
        const uint32_t bbase = sbase + ((2 + buf) * TILE_WORDS) * 4;
        const bool has = (t + 1 < NCHUNKS);
        const int k0n = (t + 1) * GKC;

        // phase-1 prefetch (j = 0,1)
        if (has) {
#pragma unroll
            for (int j = 0; j < 2; j++) {
                int idx = tid + j * 256;
                int row = idx >> 3, c = idx & 7;
                pa[j] = *(const float4*)(A + (size_t)(m0 + row) * DIMN + k0n + c * 4);
                pb[j] = *(const float4*)(B + (size_t)(n0 + row) * DIMN + k0n + c * 4);
            }
        }

        // compute k8-halves 0,1
#pragma unroll
        for (int s = 0; s < 2; s++) {
            const int kb = s * 8;
            uint32_t af[4][4];
#pragma unroll
            for (int mt = 0; mt < 4; mt++) {
                const uint32_t addr = abase
                    + (uint32_t)(((wm0 + mt * 16) * LDS_STRIDE + kb) * 4) + a_lane_off;
                ldsm_x4(af[mt][0], af[mt][1], af[mt][2], af[mt][3], addr);
            }
            uint32_t bf[4][2];
#pragma unroll
            for (int np = 0; np < 2; np++) {
                const uint32_t addr = bbase
                    + (uint32_t)(((wn0 + np * 16) * LDS_STRIDE + kb) * 4) + b_lane_off;
                ldsm_x4(bf[2 * np][0], bf[2 * np][1], bf[2 * np + 1][0], bf[2 * np + 1][1], addr);
            }
#pragma unroll
            for (int mt = 0; mt < 4; mt++)
#pragma unroll
                for (int nt = 0; nt < 4; nt++) mma_tf32(acc[mt][nt], af[mt], bf[nt]);
        }

        // phase-1 store; phase-2 prefetch (j = 2,3)
        if (has) {
            uint32_t* As = sm + nbuf * TILE_WORDS;
            uint32_t* Bs = sm + (2 + nbuf) * TILE_WORDS;
#pragma unroll
            for (int j = 0; j < 2; j++) {
                int idx = tid + j * 256;
                int row = idx >> 3, c = idx & 7;
                uint4 ua = make_uint4(f2tf32(pa[j].x), f2tf32(pa[j].y), f2tf32(pa[j].z), f2tf32(pa[j].w));
                uint4 ub = make_uint4(f2tf32(pb[j].x), f2tf32(pb[j].y), f2tf32(pb[j].z), f2tf32(pb[j].w));
                *(uint4*)(As + row * LDS_STRIDE + c * 4) = ua;
                *(uint4*)(Bs + row * LDS_STRIDE + c * 4) = ub;
            }
#pragma unroll
            for (int j = 0; j < 2; j++) {
                int idx = tid + (j + 2) * 256;
                int row = idx >> 3, c = idx & 7;
                pa[j] = *(const float4*)(A + (size_t)(m0 + row) * DIMN + k0n + c * 4);
                pb[j] = *(const float4*)(B + (size_t)(n0 + row) * DIMN + k0n + c * 4);
            }
        }

        // compute k8-halves 2,3
#pragma unroll
        for (int s = 2; s < 4; s++) {
            const int kb = s * 8;
            uint32_t af[4][4];
#pragma unroll
            for (int mt = 0; mt < 4; mt++) {
                const uint32_t addr = abase
                    + (uint32_t)(((wm0 + mt * 16) * LDS_STRIDE + kb) * 4) + a_lane_off;
                ldsm_x4(af[mt][0], af[mt][1], af[mt][2], af[mt][3], addr);
            }
            uint32_t bf[4][2];
#pragma unroll
            for (int np = 0; np < 2; np++) {
                const uint32_t addr = bbase
                    + (uint32_t)(((wn0 + np * 16) * LDS_STRIDE + kb) * 4) + b_lane_off;
                ldsm_x4(bf[2 * np][0], bf[2 * np][1], bf[2 * np + 1][0], bf[2 * np + 1][1], addr);
            }
#pragma unroll
            for (int mt = 0; mt < 4; mt++)
#pragma unroll
                for (int nt = 0; nt < 4; nt++) mma_tf32(acc[mt][nt], af[mt], bf[nt]);
        }

        // phase-2 store
        if (has) {
            uint32_t* As = sm + nbuf * TILE_WORDS;
            uint32_t* Bs = sm + (2 + nbuf) * TILE_WORDS;
#pragma unroll
            for (int j = 0; j < 2; j++) {
                int idx = tid + (j + 2) * 256;
                int row = idx >> 3, c = idx & 7;
                uint4 ua = make_uint4(f2tf32(pa[j].x), f2tf32(pa[j].y), f2tf32(pa[j].z), f2tf32(pa[j].w));
                uint4 ub = make_uint4(f2tf32(pb[j].x), f2tf32(pb[j].y), f2tf32(pb[j].z), f2tf32(pb[j].w));
                *(uint4*)(As + row * LDS_STRIDE + c * 4) = ua;
                *(uint4*)(Bs + row * LDS_STRIDE + c * 4) = ub;
            }
        }
        __syncthreads();
    }

    // epilogue: write C + |v| partial
    float asum = 0.f;
#pragma unroll
    for (int mt = 0; mt < 4; mt++) {
        const int r0 = m0 + wm0 + mt * 16 + gid;
        const int r1 = r0 + 8;
#pragma unroll
        for (int nt = 0; nt < 4; nt++) {
            const int cc = n0 + wn0 + nt * 8 + tig * 2;
            float c0 = acc[mt][nt][0], c1 = acc[mt][nt][1];
            float c2 = acc[mt][nt][2], c3 = acc[mt][nt][3];
            *(float2*)(C + (size_t)r0 * DIMN + cc) = make_float2(c0, c1);
            *(float2*)(C + (size_t)r1 * DIMN + cc) = make_float2(c2, c3);
            asum += fabsf(c0) + fabsf(c1) + fabsf(c2) + fabsf(c3);
        }
    }
#pragma unroll
    for (int o = 16; o; o >>= 1) asum += __shfl_down_sync(0xffffffffu, asum, o);
    if (lane == 0) s_red[wid] = asum;
    __syncthreads();
    if (tid == 0) {
        float s = 0.f;
        for (int i = 0; i < 8; i++) s += s_red[i];
        g_pabs[blockIdx.y * gridDim.x + blockIdx.x] = s;
    }
}

// ============================ regulator ============================
__device__ __forceinline__ double blockReduce256d(double v, double* sh) {
#pragma unroll
    for (int o = 16; o; o >>= 1) v += __shfl_down_sync(0xffffffffu, v, o);
    if ((threadIdx.x & 31) == 0) sh[threadIdx.x >> 5] = v;
    __syncthreads();
    double r = 0.0;
    if (threadIdx.x == 0)
        for (int i = 0; i < 8; i++) r += sh[i];
    __syncthreads();
    return r;
}

__global__ __launch_bounds__(256) void k_regulator(const float* __restrict__ r1w,
                                                   const float* __restrict__ r1b,
                                                   const float* __restrict__ lng,
                                                   const float* __restrict__ lnb,
                                                   const float* __restrict__ r2w,
                                                   const float* __restrict__ r2b) {
    __shared__ double sh[8];
    const int tid = threadIdx.x;
    double a = 0, b = 0, c = 0, d = 0, e = 0;
    for (int i = tid; i < 1024; i += 256) { a += (double)g_px[i]; b += (double)g_pxx[i]; }
    for (int i = tid; i < 512; i += 256)  { c += (double)g_pw[i]; d += (double)g_pf[i]; }
    for (int i = tid; i < 2048; i += 256) { e += (double)g_pabs[i]; }
    a = blockReduce256d(a, sh);
    b = blockReduce256d(b, sh);
    c = blockReduce256d(c, sh);
    d = blockReduce256d(d, sh);
    e = blockReduce256d(e, sh);
    if (tid == 0) {
        const double cnt = (double)NR * (double)DIMN;
        double mean = a / cnt;
        float stress = (float)(b / cnt - mean * mean);
        float excit  = (float)(e / cnt);
        float fatig  = sqrtf((float)c);
        float sig[3] = {stress, excit, fatig};
        float h[16];
        float mu = 0.f;
#pragma unroll
        for (int i = 0; i < 16; i++) {
            h[i] = r1b[i] + sig[0] * r1w[i * 3 + 0] + sig[1] * r1w[i * 3 + 1] + sig[2] * r1w[i * 3 + 2];
            mu += h[i];
        }
        mu *= (1.0f / 16.0f);
        float var = 0.f;
#pragma unroll
        for (int i = 0; i < 16; i++) { float dd = h[i] - mu; var += dd * dd; }
        var *= (1.0f / 16.0f);
        float rstd = rsqrtf(var + LN_EPS);
#pragma unroll
        for (int i = 0; i < 16; i++) h[i] = tanhf((h[i] - mu) * rstd * lng[i] + lnb[i]);
#pragma unroll
        for (int i = 0; i < 3; i++) {
            float s = r2b[i];
#pragma unroll
            for (int j = 0; j < 16; j++) s += h[j] * r2w[i * 16 + j];
            g_ctrl[i] = sigmoidf_(s);
        }
        g_flag = (d > 0.0) ? 1 : 0;
    }
}

// ============================ flag-gated general fast-weight path ============================
__global__ __launch_bounds__(256, 2) void sgemm_nt_flag(const float* __restrict__ A,
                                                        const float* __restrict__ B,
                                                        float* __restrict__ C,
                                                        int M, int N, int K) {
    if (g_flag == 0) return;
    constexpr int BM = 128, BN = 128, BK = 8;
    __shared__ float As[2][BK][BM];
    __shared__ float Bs[2][BK][BN];
    const int tid = threadIdx.x;
    const int m0 = blockIdx.y * BM;
    const int n0 = blockIdx.x * BN;
    const int lr = tid >> 1;
    const int lc = (tid & 1) * 4;
    const int tx = tid & 15;
    const int ty = tid >> 4;
    const float* Aptr = A + (size_t)(m0 + lr) * K + lc;
    const float* Bptr = B + (size_t)(n0 + lr) * K + lc;
    float acc[8][8] = {};
    float4 pa = *(const float4*)Aptr;
    float4 pb = *(const float4*)Bptr;
    As[0][lc + 0][lr] = pa.x; As[0][lc + 1][lr] = pa.y; As[0][lc + 2][lr] = pa.z; As[0][lc + 3][lr] = pa.w;
    Bs[0][lc + 0][lr] = pb.x; Bs[0][lc + 1][lr] = pb.y; Bs[0][lc + 2][lr] = pb.z; Bs[0][lc + 3][lr] = pb.w;
    __syncthreads();
    const int T = K / BK;
    int buf = 0;
    for (int t = 0; t < T; ++t) {
        const bool has = (t + 1 < T);
        if (has) {
            pa = *(const float4*)(Aptr + (t + 1) * BK);
            pb = *(const float4*)(Bptr + (t + 1) * BK);
        }
#pragma unroll
        for (int k = 0; k < BK; ++k) {
            float4 a0 = *(const float4*)&As[buf][k][ty * 8];
            float4 a1 = *(const float4*)&As[buf][k][ty * 8 + 4];
            float4 b0 = *(const float4*)&Bs[buf][k][tx * 8];
            float4 b1 = *(const float4*)&Bs[buf][k][tx * 8 + 4];
            float av[8] = {a0.x, a0.y, a0.z, a0.w, a1.x, a1.y, a1.z, a1.w};
            float bv[8] = {b0.x, b0.y, b0.z, b0.w, b1.x, b1.y, b1.z, b1.w};
#pragma unroll
            for (int i = 0; i < 8; i++)
#pragma unroll
                for (int j = 0; j < 8; j++) acc[i][j] += av[i] * bv[j];
        }
        if (has) {
            int w = buf ^ 1;
            As[w][lc + 0][lr] = pa.x; As[w][lc + 1][lr] = pa.y; As[w][lc + 2][lr] = pa.z; As[w][lc + 3][lr] = pa.w;
            Bs[w][lc + 0][lr] = pb.x; Bs[w][lc + 1][lr] = pb.y; Bs[w][lc + 2][lr] = pb.z; Bs[w][lc + 3][lr] = pb.w;
            __syncthreads();
            buf = w;
        }
    }
#pragma unroll
    for (int i = 0; i < 8; i++) {
        size_t off = (size_t)(m0 + ty * 8 + i) * N + n0 + tx * 8;
        *(float4*)&C[off]     = make_float4(acc[i][0], acc[i][1], acc[i][2], acc[i][3]);
        *(float4*)&C[off + 4] = make_float4(acc[i][4], acc[i][5], acc[i][6], acc[i][7]);
    }
}

__global__ __launch_bounds__(256) void k_colsq() {
    if (g_flag == 0) return;
    const int j = blockIdx.x;
    float s = 0.f;
    for (int i = threadIdx.x; i < NR; i += blockDim.x) {
        float t = g_y[(size_t)i * DIMN + j];
        s += t * t;
    }
#pragma unroll
    for (int o = 16; o; o >>= 1) s += __shfl_down_sync(0xffffffffu, s, o);
    __shared__ float sh[8];
    if ((threadIdx.x & 31) == 0) sh[threadIdx.x >> 5] = s;
    __syncthreads();
    if (threadIdx.x == 0) {
        float t = 0.f;
        for (int i = 0; i < 8; i++) t += sh[i];
        g_colsq[j] = t;
    }
}

__global__ __launch_bounds__(256) void k_hebb(const float* __restrict__ Bx) {
    if (g_flag == 0) return;
    __shared__ float As[16][64];
    __shared__ float Bs[16][64];
    const int tid = threadIdx.x;
    const int m0 = blockIdx.y * 64, n0 = blockIdx.x * 64;
    const int lk = tid >> 4;
    const int lm = (tid & 15) * 4;
    const int tx = tid & 15, ty = tid >> 4;
    float acc[4][4] = {};
    for (int k0 = 0; k0 < NR; k0 += 16) {
        float4 a = *(const float4*)&g_y[(size_t)(k0 + lk) * DIMN + m0 + lm];
        float4 b = *(const float4*)&Bx[(size_t)(k0 + lk) * DIMN + n0 + lm];
        *(float4*)&As[lk][lm] = a;
        *(float4*)&Bs[lk][lm] = b;
        __syncthreads();
#pragma unroll
        for (int k = 0; k < 16; k++) {
            float av[4], bv[4];
#pragma unroll
            for (int i = 0; i < 4; i++) { av[i] = As[k][ty * 4 + i]; bv[i] = Bs[k][tx * 4 + i]; }
#pragma unroll
            for (int i = 0; i < 4; i++)
#pragma unroll
                for (int j = 0; j < 4; j++) acc[i][j] += av[i] * bv[j];
        }
        __syncthreads();
    }
    const float scale = 1.0f / (float)NR;
#pragma unroll
    for (int i = 0; i < 4; i++)
#pragma unroll
        for (int j = 0; j < 4; j++)
            g_hebb[(size_t)(m0 + ty * 4 + i) * DIMN + n0 + tx * 4 + j] = acc[i][j] * scale;
}

__global__ __launch_bounds__(256) void k_wfnew(const float* __restrict__ wf) {
    if (g_flag == 0) return;
    const float rate = g_ctrl[1] * 0.1f;
    const float invn = 1.0f / (float)NR;
    for (size_t idx = (size_t)blockIdx.x * blockDim.x + threadIdx.x;
         idx < (size_t)DIMN * DIMN; idx += (size_t)gridDim.x * blockDim.x) {
        int j = (int)(idx / DIMN);
        float w = wf[idx];
        float forget = g_colsq[j] * invn * w;
        g_wfnew[idx] = w + tanhf(g_hebb[idx] - forget) * rate;
    }
}

// ============================ fused gate + epilogue ============================
__global__ __launch_bounds__(256) void k_finalize(const float* __restrict__ gw,
                                                  const float* __restrict__ gb,
                                                  float* __restrict__ out) {
    __shared__ float row[DIMN];
    __shared__ float red[8];
    __shared__ float s_gate;
    const int r = blockIdx.x;
    const float4* vrow = (const float4*)(g_v + (size_t)r * DIMN);
    const float4* gw4 = (const float4*)gw;
    float p = 0.f;
    for (int i = threadIdx.x; i < DIMN / 4; i += 256) {
        float4 t = vrow[i];
        float4 g = gw4[i];
        ((float4*)row)[i] = t;
        p += t.x * g.x + t.y * g.y + t.z * g.z + t.w * g.w;
    }
#pragma unroll
    for (int o = 16; o; o >>= 1) p += __shfl_down_sync(0xffffffffu, p, o);
    if ((threadIdx.x & 31) == 0) red[threadIdx.x >> 5] = p;
    __syncthreads();
    if (threadIdx.x == 0) {
        float s = 0.f;
        for (int i = 0; i < 8; i++) s += red[i];
        s_gate = g_ctrl[0] * sigmoidf_(s + gb[0]);
    }
    __syncthreads();
    const float gate = s_gate;
    const int flag = g_flag;
    const float c2 = g_ctrl[2];
    float4* o4 = (float4*)(out + (size_t)r * DIMN);
    const float4* f4 = (const float4*)(g_fast + (size_t)r * DIMN);
    for (int i = threadIdx.x; i < DIMN / 4; i += 256) {
        float4 t = ((float4*)row)[i];
        if (flag) {
            float4 f = f4[i];
            t.x += f.x * c2; t.y += f.y * c2; t.z += f.z * c2; t.w += f.w * c2;
        }
        t.x *= gate; t.y *= gate; t.z *= gate; t.w *= gate;
        o4[i] = t;
    }
}

// ============================ launch ============================
extern "C" void kernel_launch(void* const* d_in, const int* in_sizes, int n_in,
                              void* d_out, int out_size) {
    const float* x     = (const float*)d_in[0];
    const float* Vw    = (const float*)d_in[1];
    const float* Wslow = (const float*)d_in[2];
    const float* gw    = (const float*)d_in[3];
    const float* gb    = (const float*)d_in[4];
    const float* r1w   = (const float*)d_in[5];
    const float* r1b   = (const float*)d_in[6];
    const float* lng   = (const float*)d_in[7];
    const float* lnb   = (const float*)d_in[8];
    const float* r2w   = (const float*)d_in[9];
    const float* r2b   = (const float*)d_in[10];
    const float* Wfast = (const float*)d_in[11];
    float* out = (float*)d_out;

    float *pv, *py, *pfast, *pwfnew;
    cudaGetSymbolAddress((void**)&pv, g_v);
    cudaGetSymbolAddress((void**)&py, g_y);
    cudaGetSymbolAddress((void**)&pfast, g_fast);
    cudaGetSymbolAddress((void**)&pwfnew, g_wfnew);

    cudaFuncSetAttribute(k_gemm_v, cudaFuncAttributeMaxDynamicSharedMemorySize, SMEM_GEMM_BYTES);

    k_stats_x<<<1024, 256>>>((const float4*)x, NR * DIMN / 4);
    k_stats_w<<<512, 256>>>((const float4*)Wslow, (const float4*)Wfast, DIMN * DIMN / 4);

    dim3 gg(DIMN / 128, NR / 128);   // (16, 128) -> 2048 CTAs
    k_gemm_v<<<gg, 256, SMEM_GEMM_BYTES>>>(x, Vw, pv);

    k_regulator<<<1, 256>>>(r1w, r1b, lng, lnb, r2w, r2b);

    // general fast-weight path; every kernel early-exits when W_fast == 0
    dim3 gv(DIMN / 128, NR / 128);
    sgemm_nt_flag<<<gv, 256>>>(x, Wfast, py, NR, DIMN, DIMN);
    k_colsq<<<DIMN, 256>>>();
    dim3 gh(DIMN / 64, DIMN / 64);
    k_hebb<<<gh, 256>>>(x);
    k_wfnew<<<4096, 256>>>(Wfast);
    sgemm_nt_flag<<<gv, 256>>>(x, pwfnew, pfast, NR, DIMN, DIMN);

    k_finalize<<<NR, 256>>>(gw, gb, out);
}